// round 7
// baseline (speedup 1.0000x reference)
#include <cuda_runtime.h>
#include <cuda_fp16.h>
#include <cstdint>

// Problem dims
#define MROWS 16384   // B*S
#define DDIM  2048
#define FDIM  128
#define DH    1024
#define SEQ   4096
#define NBATCH 4

// ======================= scratch (static, no allocs) =======================
__device__ __align__(256) float g_sc[(size_t)MROWS * FDIM];
__device__ __align__(256) float g_V [(size_t)MROWS * FDIM];
__device__ __align__(256) float g_o2[(size_t)MROWS * DDIM];
__device__ __align__(256) float g_bqk[256];
__device__ __align__(256) float g_bpj[DDIM];
// fp16 activations
__device__ __align__(256) __half g_xh [(size_t)MROWS * DDIM];
__device__ __align__(256) __half g_Hh [(size_t)MROWS * DDIM];
__device__ __align__(256) __half g_xch[(size_t)MROWS * FDIM];
__device__ __align__(256) __half g_gh [(size_t)MROWS * DH];
// fp16 transposed weights W^T [N, K] (K contiguous)
__device__ __align__(256) __half g_wqk[(size_t)256 * DDIM];   // interleaved q/k cols
__device__ __align__(256) __half g_wlo[(size_t)DDIM * DDIM];
__device__ __align__(256) __half g_wlp[(size_t)FDIM * DDIM];
__device__ __align__(256) __half g_wpj[(size_t)DDIM * FDIM];  // interleaved a/b cols
__device__ __align__(256) __half g_wo [(size_t)DDIM * DH];

// ======================= helpers =======================
__device__ __forceinline__ uint32_t smem_u32(const void* p) {
    uint32_t a;
    asm("{ .reg .u64 t; cvta.to.shared.u64 t, %1; cvt.u32.u64 %0, t; }" : "=r"(a) : "l"(p));
    return a;
}
__device__ __forceinline__ void ldx4(uint32_t* r, uint32_t addr) {
    asm volatile("ldmatrix.sync.aligned.m8n8.x4.shared.b16 {%0,%1,%2,%3}, [%4];"
        : "=r"(r[0]), "=r"(r[1]), "=r"(r[2]), "=r"(r[3]) : "r"(addr));
}
__device__ __forceinline__ void mma_fp16(float* c, const uint32_t* a, const uint32_t* b) {
    asm volatile("mma.sync.aligned.m16n8k16.row.col.f32.f16.f16.f32 "
        "{%0,%1,%2,%3}, {%4,%5,%6,%7}, {%8,%9}, {%0,%1,%2,%3};"
        : "+f"(c[0]), "+f"(c[1]), "+f"(c[2]), "+f"(c[3])
        : "r"(a[0]), "r"(a[1]), "r"(a[2]), "r"(a[3]), "r"(b[0]), "r"(b[1]));
}
__device__ __forceinline__ float sigm(float x) { return 1.0f / (1.0f + __expf(-x)); }
__device__ __forceinline__ float gelu_f(float x) {
    float z  = 0.7978845608028654f * (x + 0.044715f * x * x * x);
    float az = fabsf(z);
    float e  = __expf(-2.0f * az);
    float t  = (1.0f - e) / (1.0f + e);
    t = copysignf(t, z);
    return 0.5f * x * (1.0f + t);
}
__device__ __forceinline__ uint32_t pack2(__half a, __half b) {
    return (uint32_t)__half_as_ushort(a) | ((uint32_t)__half_as_ushort(b) << 16);
}

// row stride in smem: 64B data (BK=32 fp16) + 16B pad -> conflict-free ldmatrix
#define RSTR 80

// ======================= fp16 HMMA GEMM (wide: 128x256, 512 thr) =============
// C[M,N] = A[M,K](fp16) @ B^T[N,K](fp16). BK=32, 4-stage cp.async pipeline.
// EPI 0: Cf = acc + bias (f32).
// EPI 1: gelu(acc+bias) -> Ch (fp16), stride N.
// EPI 2: gate: cols interleaved (a,b); silu(a)*b -> Ch (fp16), stride N/2.
#define A512   10240          // 128*RSTR
#define STG512 30720
#define SM512  122880         // 4 stages

template <int EPI>
__global__ void __launch_bounds__(512, 1) hgemm512(
    const __half* __restrict__ Ap, const __half* __restrict__ Bp,
    const float* __restrict__ bias,
    float* __restrict__ Cf, __half* __restrict__ Ch,
    int N, int K)
{
    extern __shared__ char smem[];
    const uint32_t sbase = smem_u32(smem);
    const int tid  = threadIdx.x;
    const int wid  = tid >> 5, lane = tid & 31;
    const long bm  = (long)blockIdx.y * 128;
    const long bn  = (long)blockIdx.x * 256;
    const int  wm  = wid >> 3, wn = wid & 7;
    const long kb  = (long)K * 2;

    const char* baseA = (const char*)Ap + bm * kb;
    const char* baseB = (const char*)Bp + bn * kb;
    const int lrow = tid >> 2, lcol = tid & 3;

    auto load_stage = [&](int kt, int buf) {
        const uint32_t so = sbase + buf * STG512;
        const long gk = (long)kt * 64 + lcol * 16;
        asm volatile("cp.async.cg.shared.global [%0], [%1], 16;"
            :: "r"(so + lrow * RSTR + lcol * 16), "l"(baseA + (long)lrow * kb + gk));
#pragma unroll
        for (int c = 0; c < 2; ++c) {
            const int row = lrow + c * 128;
            asm volatile("cp.async.cg.shared.global [%0], [%1], 16;"
                :: "r"(so + A512 + row * RSTR + lcol * 16), "l"(baseB + (long)row * kb + gk));
        }
        asm volatile("cp.async.commit_group;" ::: "memory");
    };

    const uint32_t g  = lane >> 3, li = lane & 7;
    const uint32_t aRow = wm * 64 + ((g & 1) << 3) + li;
    const uint32_t aCol = (g >> 1) << 4;
    const uint32_t bRow = wn * 32 + ((g >> 1) << 3) + li;
    const uint32_t bCol = (g & 1) << 4;

    float acc[4][4][4];
#pragma unroll
    for (int i = 0; i < 4; ++i)
#pragma unroll
        for (int j = 0; j < 4; ++j)
#pragma unroll
            for (int q = 0; q < 4; ++q) acc[i][j][q] = 0.f;

    const int nk = K >> 5;
    load_stage(0, 0);
    if (nk > 1) load_stage(1, 1);
    if (nk > 2) load_stage(2, 2);

    for (int kt = 0; kt < nk; ++kt) {
        if (kt <= nk - 3)      asm volatile("cp.async.wait_group 2;" ::: "memory");
        else if (kt == nk - 2) asm volatile("cp.async.wait_group 1;" ::: "memory");
        else                   asm volatile("cp.async.wait_group 0;" ::: "memory");
        __syncthreads();
        if (kt + 3 < nk) load_stage(kt + 3, (kt + 3) & 3);

        const uint32_t so = sbase + (kt & 3) * STG512;
#pragma unroll
        for (int kk = 0; kk < 2; ++kk) {
            uint32_t ah[4][4], bh[4][2];
#pragma unroll
            for (int mt = 0; mt < 4; ++mt)
                ldx4(ah[mt], so + (aRow + mt * 16) * RSTR + kk * 32 + aCol);
#pragma unroll
            for (int p = 0; p < 2; ++p) {
                uint32_t r[4];
                ldx4(r, so + A512 + (bRow + p * 16) * RSTR + kk * 32 + bCol);
                bh[2*p][0] = r[0]; bh[2*p][1] = r[1];
                bh[2*p+1][0] = r[2]; bh[2*p+1][1] = r[3];
            }
#pragma unroll
            for (int mt = 0; mt < 4; ++mt)
#pragma unroll
                for (int nt = 0; nt < 4; ++nt)
                    mma_fp16(acc[mt][nt], ah[mt], bh[nt]);
        }
    }

#pragma unroll
    for (int mt = 0; mt < 4; ++mt) {
        const long r0 = bm + wm * 64 + mt * 16 + (lane >> 2);
#pragma unroll
        for (int nt = 0; nt < 4; ++nt) {
            const long cc = bn + wn * 32 + nt * 8 + (lane & 3) * 2;
            const float2 bv = *(const float2*)(bias + cc);
            float v0 = acc[mt][nt][0] + bv.x, v1 = acc[mt][nt][1] + bv.y;
            float v2 = acc[mt][nt][2] + bv.x, v3 = acc[mt][nt][3] + bv.y;
            if (EPI == 0) {
                *(float2*)(Cf + r0 * N + cc)       = make_float2(v0, v1);
                *(float2*)(Cf + (r0 + 8) * N + cc) = make_float2(v2, v3);
            } else if (EPI == 1) {
                *(uint32_t*)(Ch + r0 * N + cc) =
                    pack2(__float2half_rn(gelu_f(v0)), __float2half_rn(gelu_f(v1)));
                *(uint32_t*)(Ch + (r0 + 8) * N + cc) =
                    pack2(__float2half_rn(gelu_f(v2)), __float2half_rn(gelu_f(v3)));
            } else {  // gate: (v0,v1)=(a,b), (v2,v3)=(a,b)
                const long j = cc >> 1, half = N >> 1;
                Ch[r0 * half + j]       = __float2half_rn((v0 * sigm(v0)) * v1);
                Ch[(r0 + 8) * half + j] = __float2half_rn((v2 * sigm(v2)) * v3);
            }
        }
    }
}

// ======================= fp16 GEMM (narrow: 128x128, 256 thr) ================
// EPI 0: Cf = acc + bias. EPI 1: score: cols interleaved (q,k);
//        sigm(q)*sigm(k) -> Cf, stride N/2.
#define STG256 20480
#define SM256  81920

template <int EPI>
__global__ void __launch_bounds__(256, 2) hgemm256(
    const __half* __restrict__ Ap, const __half* __restrict__ Bp,
    const float* __restrict__ bias, float* __restrict__ Cf,
    int N, int K)
{
    extern __shared__ char smem[];
    const uint32_t sbase = smem_u32(smem);
    const int tid  = threadIdx.x;
    const int wid  = tid >> 5, lane = tid & 31;
    const long bm  = (long)blockIdx.y * 128;
    const long bn  = (long)blockIdx.x * 128;
    const int  wm  = wid >> 2, wn = wid & 3;
    const long kb  = (long)K * 2;

    const char* baseA = (const char*)Ap + bm * kb;
    const char* baseB = (const char*)Bp + bn * kb;
    const int lrow0 = tid >> 2, lcol = tid & 3;

    auto load_stage = [&](int kt, int buf) {
        const uint32_t so = sbase + buf * STG256;
        const long gk = (long)kt * 64 + lcol * 16;
#pragma unroll
        for (int c = 0; c < 2; ++c) {
            const int row = lrow0 + c * 64;
            asm volatile("cp.async.cg.shared.global [%0], [%1], 16;"
                :: "r"(so + row * RSTR + lcol * 16), "l"(baseA + (long)row * kb + gk));
            asm volatile("cp.async.cg.shared.global [%0], [%1], 16;"
                :: "r"(so + A512 + row * RSTR + lcol * 16), "l"(baseB + (long)row * kb + gk));
        }
        asm volatile("cp.async.commit_group;" ::: "memory");
    };

    const uint32_t g  = lane >> 3, li = lane & 7;
    const uint32_t aRow = wm * 64 + ((g & 1) << 3) + li;
    const uint32_t aCol = (g >> 1) << 4;
    const uint32_t bRow = wn * 32 + ((g >> 1) << 3) + li;
    const uint32_t bCol = (g & 1) << 4;

    float acc[4][4][4];
#pragma unroll
    for (int i = 0; i < 4; ++i)
#pragma unroll
        for (int j = 0; j < 4; ++j)
#pragma unroll
            for (int q = 0; q < 4; ++q) acc[i][j][q] = 0.f;

    const int nk = K >> 5;
    load_stage(0, 0);
    if (nk > 1) load_stage(1, 1);
    if (nk > 2) load_stage(2, 2);

    for (int kt = 0; kt < nk; ++kt) {
        if (kt <= nk - 3)      asm volatile("cp.async.wait_group 2;" ::: "memory");
        else if (kt == nk - 2) asm volatile("cp.async.wait_group 1;" ::: "memory");
        else                   asm volatile("cp.async.wait_group 0;" ::: "memory");
        __syncthreads();
        if (kt + 3 < nk) load_stage(kt + 3, (kt + 3) & 3);

        const uint32_t so = sbase + (kt & 3) * STG256;
#pragma unroll
        for (int kk = 0; kk < 2; ++kk) {
            uint32_t ah[4][4], bh[4][2];
#pragma unroll
            for (int mt = 0; mt < 4; ++mt)
                ldx4(ah[mt], so + (aRow + mt * 16) * RSTR + kk * 32 + aCol);
#pragma unroll
            for (int p = 0; p < 2; ++p) {
                uint32_t r[4];
                ldx4(r, so + A512 + (bRow + p * 16) * RSTR + kk * 32 + bCol);
                bh[2*p][0] = r[0]; bh[2*p][1] = r[1];
                bh[2*p+1][0] = r[2]; bh[2*p+1][1] = r[3];
            }
#pragma unroll
            for (int mt = 0; mt < 4; ++mt)
#pragma unroll
                for (int nt = 0; nt < 4; ++nt)
                    mma_fp16(acc[mt][nt], ah[mt], bh[nt]);
        }
    }

#pragma unroll
    for (int mt = 0; mt < 4; ++mt) {
        const long r0 = bm + wm * 64 + mt * 16 + (lane >> 2);
#pragma unroll
        for (int nt = 0; nt < 4; ++nt) {
            const long cc = bn + wn * 32 + nt * 8 + (lane & 3) * 2;
            const float2 bv = *(const float2*)(bias + cc);
            float v0 = acc[mt][nt][0] + bv.x, v1 = acc[mt][nt][1] + bv.y;
            float v2 = acc[mt][nt][2] + bv.x, v3 = acc[mt][nt][3] + bv.y;
            if (EPI == 0) {
                *(float2*)(Cf + r0 * N + cc)       = make_float2(v0, v1);
                *(float2*)(Cf + (r0 + 8) * N + cc) = make_float2(v2, v3);
            } else {  // score: (q,k) pairs
                const long j = cc >> 1, half = N >> 1;
                Cf[r0 * half + j]       = sigm(v0) * sigm(v1);
                Cf[(r0 + 8) * half + j] = sigm(v2) * sigm(v3);
            }
        }
    }
}

// ======================= weight transpose -> fp16 =======================
// mode 0: row = rowoff + n ; mode 1: row = 2n + rowoff (q/k interleave)
// mode 2: row = n<N/2 ? 2n : 2(n-N/2)+1 (gate a/b interleave)
__global__ void tsplit_kernel(const float* __restrict__ W,
                              __half* __restrict__ th, int K, int N,
                              int mode, int rowoff)
{
    __shared__ float t[32][33];
    const int k0 = blockIdx.y * 32, n0 = blockIdx.x * 32;
    const int tx = threadIdx.x, ty = threadIdx.y;
#pragma unroll
    for (int i = ty; i < 32; i += 8)
        t[i][tx] = W[(long)(k0 + i) * N + n0 + tx];
    __syncthreads();
#pragma unroll
    for (int i = ty; i < 32; i += 8) {
        const int n = n0 + i;
        long row;
        if (mode == 0)      row = rowoff + n;
        else if (mode == 1) row = 2 * (long)n + rowoff;
        else                row = (n < (N >> 1)) ? 2 * (long)n : 2 * (long)(n - (N >> 1)) + 1;
        th[row * (long)K + (k0 + tx)] = __float2half_rn(t[tx][i]);
    }
}

// ======================= x -> fp16 =======================
__global__ void cvt_kernel(const float* __restrict__ x, __half* __restrict__ h, long n4)
{
    long i = (long)blockIdx.x * blockDim.x + threadIdx.x;
    if (i >= n4) return;
    float4 v = ((const float4*)x)[i];
    ((uint2*)h)[i] = make_uint2(
        pack2(__float2half_rn(v.x), __float2half_rn(v.y)),
        pack2(__float2half_rn(v.z), __float2half_rn(v.w)));
}

__global__ void bqk_kernel(const float* __restrict__ Qb, const float* __restrict__ Kb,
                           float* __restrict__ b)
{
    int i = threadIdx.x;  // 256
    b[i] = (i & 1) ? Kb[i >> 1] : Qb[i >> 1];
}

__global__ void bpj_kernel(const float* __restrict__ pb, float* __restrict__ b)
{
    int i = blockIdx.x * blockDim.x + threadIdx.x;  // 2048
    b[i] = pb[(i >> 1) + (i & 1) * DH];
}

// ============== EMA scan + mean/clip * V -> fp16 (fused) ==============
#define EMA_CHUNK 128
#define EMA_WARM  256
__global__ void ema_fused(const float* __restrict__ sc, const float* __restrict__ V,
                          __half* __restrict__ xch)
{
    const int b  = blockIdx.y;
    const int t0 = blockIdx.x * EMA_CHUNK;
    const int f  = threadIdx.x;  // 128
    const float* sb = sc  + ((long)b * SEQ) * FDIM + f;
    const float* Vb = V   + ((long)b * SEQ) * FDIM + f;
    __half*      xb = xch + ((long)b * SEQ) * FDIM + f;
    __shared__ float ws[4];

    auto emit = [&](int t, float e) {
        float s = e;
#pragma unroll
        for (int o = 16; o; o >>= 1) s += __shfl_xor_sync(0xffffffffu, s, o);
        if ((f & 31) == 0) ws[f >> 5] = s;
        __syncthreads();
        float tot = ws[0] + ws[1] + ws[2] + ws[3];
        __syncthreads();
        float denom = fmaxf(tot * (1.0f / 128.0f), 1e-6f);
        float c = fminf(fmaxf(e / denom, -5.0f), 5.0f);
        xb[(long)t * FDIM] = __float2half_rn(c * Vb[(long)t * FDIM]);
    };

    int   t = t0 - EMA_WARM;
    float prev;
    if (t <= 0) {
        prev = sb[0];
        if (t0 == 0) emit(0, prev);
        t = 1;
    } else {
        prev = 0.0f;
    }
    const int tend = t0 + EMA_CHUNK;
    for (; t < tend; ++t) {
        float s = sb[(long)t * FDIM];
        prev = 0.15f * s + 0.85f * prev;
        if (t >= t0) emit(t, prev);
    }
}

// ======================= residual + LayerNorm =======================
__global__ void __launch_bounds__(256) ln_kernel(
    const float* __restrict__ o2, const float* __restrict__ x,
    const float* __restrict__ gamma, const float* __restrict__ beta,
    float* __restrict__ y)
{
    __shared__ float ws[8];
    const long row = blockIdx.x;
    const int  tid = threadIdx.x;
    const float* pr = o2 + row * DDIM;
    const float* px = x  + row * DDIM;
    const int c0 = tid * 4;
    const int c1 = 1024 + tid * 4;

    float4 a0 = *(const float4*)(pr + c0), r0 = *(const float4*)(px + c0);
    float4 a1 = *(const float4*)(pr + c1), r1 = *(const float4*)(px + c1);
    float h[8] = { a0.x + r0.x, a0.y + r0.y, a0.z + r0.z, a0.w + r0.w,
                   a1.x + r1.x, a1.y + r1.y, a1.z + r1.z, a1.w + r1.w };

    float s = 0.f;
#pragma unroll
    for (int i = 0; i < 8; ++i) s += h[i];
#pragma unroll
    for (int o = 16; o; o >>= 1) s += __shfl_xor_sync(0xffffffffu, s, o);
    if ((tid & 31) == 0) ws[tid >> 5] = s;
    __syncthreads();
    float tot = 0.f;
#pragma unroll
    for (int i = 0; i < 8; ++i) tot += ws[i];
    const float mu = tot * (1.0f / 2048.0f);
    __syncthreads();

    float sq = 0.f;
#pragma unroll
    for (int i = 0; i < 8; ++i) { float d = h[i] - mu; sq += d * d; }
#pragma unroll
    for (int o = 16; o; o >>= 1) sq += __shfl_xor_sync(0xffffffffu, sq, o);
    if ((tid & 31) == 0) ws[tid >> 5] = sq;
    __syncthreads();
    float tot2 = 0.f;
#pragma unroll
    for (int i = 0; i < 8; ++i) tot2 += ws[i];
    const float inv = rsqrtf(tot2 * (1.0f / 2048.0f) + 1e-5f);

    float4 g0 = *(const float4*)(gamma + c0), g1 = *(const float4*)(gamma + c1);
    float4 b0 = *(const float4*)(beta  + c0), b1 = *(const float4*)(beta  + c1);
    float4 y0, y1;
    y0.x = (h[0] - mu) * inv * g0.x + b0.x;
    y0.y = (h[1] - mu) * inv * g0.y + b0.y;
    y0.z = (h[2] - mu) * inv * g0.z + b0.z;
    y0.w = (h[3] - mu) * inv * g0.w + b0.w;
    y1.x = (h[4] - mu) * inv * g1.x + b1.x;
    y1.y = (h[5] - mu) * inv * g1.y + b1.y;
    y1.z = (h[6] - mu) * inv * g1.z + b1.z;
    y1.w = (h[7] - mu) * inv * g1.w + b1.w;
    *(float4*)(y + row * DDIM + c0) = y0;
    *(float4*)(y + row * DDIM + c1) = y1;
}

// ======================= launch =======================
extern "C" void kernel_launch(void* const* d_in, const int* in_sizes, int n_in,
                              void* d_out, int out_size)
{
    const float* x      = (const float*)d_in[0];
    const float* Qw     = (const float*)d_in[1];
    const float* Qb     = (const float*)d_in[2];
    const float* Kw     = (const float*)d_in[3];
    const float* Kb     = (const float*)d_in[4];
    const float* low    = (const float*)d_in[5];
    const float* lob    = (const float*)d_in[6];
    const float* lopw   = (const float*)d_in[7];
    const float* lopb   = (const float*)d_in[8];
    const float* projw  = (const float*)d_in[9];
    const float* projb  = (const float*)d_in[10];
    const float* Ow     = (const float*)d_in[11];
    const float* Ob     = (const float*)d_in[12];
    const float* gamma  = (const float*)d_in[13];
    const float* beta   = (const float*)d_in[14];
    float* out = (float*)d_out;

    float *sc, *V, *o2, *bqk, *bpj;
    __half *xh, *Hh, *xch, *gh;
    __half *wqk, *wlo, *wlp, *wpj, *wo;
    cudaGetSymbolAddress((void**)&sc,  g_sc);
    cudaGetSymbolAddress((void**)&V,   g_V);
    cudaGetSymbolAddress((void**)&o2,  g_o2);
    cudaGetSymbolAddress((void**)&bqk, g_bqk);
    cudaGetSymbolAddress((void**)&bpj, g_bpj);
    cudaGetSymbolAddress((void**)&xh,  g_xh);
    cudaGetSymbolAddress((void**)&Hh,  g_Hh);
    cudaGetSymbolAddress((void**)&xch, g_xch);
    cudaGetSymbolAddress((void**)&gh,  g_gh);
    cudaGetSymbolAddress((void**)&wqk, g_wqk);
    cudaGetSymbolAddress((void**)&wlo, g_wlo);
    cudaGetSymbolAddress((void**)&wlp, g_wlp);
    cudaGetSymbolAddress((void**)&wpj, g_wpj);
    cudaGetSymbolAddress((void**)&wo,  g_wo);

    cudaFuncSetAttribute(hgemm512<0>, cudaFuncAttributeMaxDynamicSharedMemorySize, SM512);
    cudaFuncSetAttribute(hgemm512<1>, cudaFuncAttributeMaxDynamicSharedMemorySize, SM512);
    cudaFuncSetAttribute(hgemm512<2>, cudaFuncAttributeMaxDynamicSharedMemorySize, SM512);
    cudaFuncSetAttribute(hgemm256<0>, cudaFuncAttributeMaxDynamicSharedMemorySize, SM256);
    cudaFuncSetAttribute(hgemm256<1>, cudaFuncAttributeMaxDynamicSharedMemorySize, SM256);

    const dim3 tb32(32, 8);
    // launches 1-5: only deps of the big H GEMM (so H is launch #6 for ncu -s 5)
    tsplit_kernel<<<dim3(DDIM/32, DDIM/32), tb32>>>(low,  wlo, DDIM, DDIM, 0, 0);  // 1
    {
        long n4 = (long)MROWS * DDIM / 4;
        cvt_kernel<<<(unsigned)((n4 + 255) / 256), 256>>>(x, xh, n4);              // 2
    }
    bqk_kernel<<<1, 256>>>(Qb, Kb, bqk);                                           // 3
    tsplit_kernel<<<dim3(FDIM/32, DDIM/32), tb32>>>(Qw, wqk, DDIM, FDIM, 1, 0);    // 4
    tsplit_kernel<<<dim3(FDIM/32, DDIM/32), tb32>>>(Kw, wqk, DDIM, FDIM, 1, 1);    // 5
    // H = gelu(x @ lo_proj_w + b) -> fp16   [launch 6 — profiled]
    hgemm512<1><<<dim3(DDIM/256, MROWS/128), 512, SM512>>>(xh, wlo, lob, nullptr, Hh, DDIM, DDIM);
    // remaining weight prep
    tsplit_kernel<<<dim3(FDIM/32, DDIM/32), tb32>>>(lopw, wlp, DDIM, FDIM, 0, 0);
    tsplit_kernel<<<dim3(DDIM/32, FDIM/32), tb32>>>(projw,wpj, FDIM, DDIM, 2, 0);
    bpj_kernel<<<DDIM/256, 256>>>(projb, bpj);
    tsplit_kernel<<<dim3(DDIM/32, DH/32),   tb32>>>(Ow, wo, DH, DDIM, 0, 0);
    // sc = sigm(q)*sigm(k), fused in qk GEMM (interleaved q/k cols)
    hgemm256<1><<<dim3(2, MROWS/128), 256, SM256>>>(xh, wqk, bqk, sc, 256, DDIM);
    // V = H @ lo_p_w + b
    hgemm256<0><<<dim3(1, MROWS/128), 256, SM256>>>(Hh, wlp, lopb, V, FDIM, DDIM);
    // EMA + mean/clip * V -> xch (fused)
    ema_fused<<<dim3(SEQ / EMA_CHUNK, NBATCH), 128>>>(sc, V, xch);
    // gh = silu(a)*b, fused in o1 GEMM (interleaved a/b cols)
    hgemm512<2><<<dim3(DDIM/256, MROWS/128), 512, SM512>>>(xch, wpj, bpj, nullptr, gh, DDIM, FDIM);
    // o2 = g @ O_w + b
    hgemm512<0><<<dim3(DDIM/256, MROWS/128), 512, SM512>>>(gh, wo, Ob, o2, nullptr, DDIM, DH);
    // residual + LN
    ln_kernel<<<MROWS, 256>>>(o2, x, gamma, beta, out);
}

// round 11
// speedup vs baseline: 1.0379x; 1.0379x over previous
#include <cuda_runtime.h>
#include <cuda_fp16.h>
#include <cstdint>

// Problem dims
#define MROWS 16384   // B*S
#define DDIM  2048
#define FDIM  128
#define DH    1024
#define SEQ   4096
#define NBATCH 4

// ======================= scratch (static, no allocs) =======================
__device__ __align__(256) float g_sc[(size_t)MROWS * FDIM];
__device__ __align__(256) float g_V [(size_t)MROWS * FDIM];
__device__ __align__(256) float g_o2[(size_t)MROWS * DDIM];
__device__ __align__(256) float g_bqk[256];
__device__ __align__(256) float g_bpj[DDIM];
// fp16 activations
__device__ __align__(256) __half g_xh [(size_t)MROWS * DDIM];
__device__ __align__(256) __half g_Hh [(size_t)MROWS * DDIM];
__device__ __align__(256) __half g_xch[(size_t)MROWS * FDIM];
__device__ __align__(256) __half g_gh [(size_t)MROWS * DH];
// fp16 transposed weights W^T [N, K] (K contiguous)
__device__ __align__(256) __half g_wqk[(size_t)256 * DDIM];   // interleaved q/k cols
__device__ __align__(256) __half g_wlo[(size_t)DDIM * DDIM];
__device__ __align__(256) __half g_wlp[(size_t)FDIM * DDIM];
__device__ __align__(256) __half g_wpj[(size_t)DDIM * FDIM];  // interleaved a/b cols
__device__ __align__(256) __half g_wo [(size_t)DDIM * DH];

// ======================= helpers =======================
__device__ __forceinline__ uint32_t smem_u32(const void* p) {
    uint32_t a;
    asm("{ .reg .u64 t; cvta.to.shared.u64 t, %1; cvt.u32.u64 %0, t; }" : "=r"(a) : "l"(p));
    return a;
}
__device__ __forceinline__ void ldx4(uint32_t* r, uint32_t addr) {
    asm volatile("ldmatrix.sync.aligned.m8n8.x4.shared.b16 {%0,%1,%2,%3}, [%4];"
        : "=r"(r[0]), "=r"(r[1]), "=r"(r[2]), "=r"(r[3]) : "r"(addr));
}
__device__ __forceinline__ void mma_fp16(float* c, const uint32_t* a, const uint32_t* b) {
    asm volatile("mma.sync.aligned.m16n8k16.row.col.f32.f16.f16.f32 "
        "{%0,%1,%2,%3}, {%4,%5,%6,%7}, {%8,%9}, {%0,%1,%2,%3};"
        : "+f"(c[0]), "+f"(c[1]), "+f"(c[2]), "+f"(c[3])
        : "r"(a[0]), "r"(a[1]), "r"(a[2]), "r"(a[3]), "r"(b[0]), "r"(b[1]));
}
__device__ __forceinline__ float sigm(float x) { return 1.0f / (1.0f + __expf(-x)); }
__device__ __forceinline__ float gelu_f(float x) {
    float z  = 0.7978845608028654f * (x + 0.044715f * x * x * x);
    float az = fabsf(z);
    float e  = __expf(-2.0f * az);
    float t  = (1.0f - e) / (1.0f + e);
    t = copysignf(t, z);
    return 0.5f * x * (1.0f + t);
}
__device__ __forceinline__ uint32_t pack2(__half a, __half b) {
    return (uint32_t)__half_as_ushort(a) | ((uint32_t)__half_as_ushort(b) << 16);
}

// row stride in smem: 64B data (BK=32 fp16) + 16B pad -> conflict-free ldmatrix
#define RSTR 80

// ======================= fp16 HMMA GEMM (wide: 128x256, 512 thr) =============
#define A512   10240          // 128*RSTR
#define STG512 30720
#define SM512  122880         // 4 stages

template <int EPI>
__global__ void __launch_bounds__(512, 1) hgemm512(
    const __half* __restrict__ Ap, const __half* __restrict__ Bp,
    const float* __restrict__ bias,
    float* __restrict__ Cf, __half* __restrict__ Ch,
    int N, int K)
{
    extern __shared__ char smem[];
    const uint32_t sbase = smem_u32(smem);
    const int tid  = threadIdx.x;
    const int wid  = tid >> 5, lane = tid & 31;
    const long bm  = (long)blockIdx.y * 128;
    const long bn  = (long)blockIdx.x * 256;
    const int  wm  = wid >> 3, wn = wid & 7;
    const long kb  = (long)K * 2;

    const char* baseA = (const char*)Ap + bm * kb;
    const char* baseB = (const char*)Bp + bn * kb;
    const int lrow = tid >> 2, lcol = tid & 3;

    auto load_stage = [&](int kt, int buf) {
        const uint32_t so = sbase + buf * STG512;
        const long gk = (long)kt * 64 + lcol * 16;
        asm volatile("cp.async.cg.shared.global [%0], [%1], 16;"
            :: "r"(so + lrow * RSTR + lcol * 16), "l"(baseA + (long)lrow * kb + gk));
#pragma unroll
        for (int c = 0; c < 2; ++c) {
            const int row = lrow + c * 128;
            asm volatile("cp.async.cg.shared.global [%0], [%1], 16;"
                :: "r"(so + A512 + row * RSTR + lcol * 16), "l"(baseB + (long)row * kb + gk));
        }
        asm volatile("cp.async.commit_group;" ::: "memory");
    };

    const uint32_t g  = lane >> 3, li = lane & 7;
    const uint32_t aRow = wm * 64 + ((g & 1) << 3) + li;
    const uint32_t aCol = (g >> 1) << 4;
    const uint32_t bRow = wn * 32 + ((g >> 1) << 3) + li;
    const uint32_t bCol = (g & 1) << 4;

    float acc[4][4][4];
#pragma unroll
    for (int i = 0; i < 4; ++i)
#pragma unroll
        for (int j = 0; j < 4; ++j)
#pragma unroll
            for (int q = 0; q < 4; ++q) acc[i][j][q] = 0.f;

    const int nk = K >> 5;
    load_stage(0, 0);
    if (nk > 1) load_stage(1, 1);
    if (nk > 2) load_stage(2, 2);

    for (int kt = 0; kt < nk; ++kt) {
        if (kt <= nk - 3)      asm volatile("cp.async.wait_group 2;" ::: "memory");
        else if (kt == nk - 2) asm volatile("cp.async.wait_group 1;" ::: "memory");
        else                   asm volatile("cp.async.wait_group 0;" ::: "memory");
        __syncthreads();
        if (kt + 3 < nk) load_stage(kt + 3, (kt + 3) & 3);

        const uint32_t so = sbase + (kt & 3) * STG512;
#pragma unroll
        for (int kk = 0; kk < 2; ++kk) {
            uint32_t ah[4][4], bh[4][2];
#pragma unroll
            for (int mt = 0; mt < 4; ++mt)
                ldx4(ah[mt], so + (aRow + mt * 16) * RSTR + kk * 32 + aCol);
#pragma unroll
            for (int p = 0; p < 2; ++p) {
                uint32_t r[4];
                ldx4(r, so + A512 + (bRow + p * 16) * RSTR + kk * 32 + bCol);
                bh[2*p][0] = r[0]; bh[2*p][1] = r[1];
                bh[2*p+1][0] = r[2]; bh[2*p+1][1] = r[3];
            }
#pragma unroll
            for (int mt = 0; mt < 4; ++mt)
#pragma unroll
                for (int nt = 0; nt < 4; ++nt)
                    mma_fp16(acc[mt][nt], ah[mt], bh[nt]);
        }
    }

    if (EPI == 2) __syncthreads();  // mainloop smem reads done before reuse

#pragma unroll
    for (int mt = 0; mt < 4; ++mt) {
        const long r0 = bm + wm * 64 + mt * 16 + (lane >> 2);
        const int  r0l = wm * 64 + mt * 16 + (lane >> 2);
#pragma unroll
        for (int nt = 0; nt < 4; ++nt) {
            const int  ccl = wn * 32 + nt * 8 + (lane & 3) * 2;
            const long cc  = bn + ccl;
            const float2 bv = *(const float2*)(bias + cc);
            float v0 = acc[mt][nt][0] + bv.x, v1 = acc[mt][nt][1] + bv.y;
            float v2 = acc[mt][nt][2] + bv.x, v3 = acc[mt][nt][3] + bv.y;
            if (EPI == 0) {
                *(float2*)(Cf + r0 * N + cc)       = make_float2(v0, v1);
                *(float2*)(Cf + (r0 + 8) * N + cc) = make_float2(v2, v3);
            } else if (EPI == 1) {
                *(uint32_t*)(Ch + r0 * N + cc) =
                    pack2(__float2half_rn(gelu_f(v0)), __float2half_rn(gelu_f(v1)));
                *(uint32_t*)(Ch + (r0 + 8) * N + cc) =
                    pack2(__float2half_rn(gelu_f(v2)), __float2half_rn(gelu_f(v3)));
            } else {  // gate -> smem tile, 272B row stride (conflict-free)
                __half* gt = (__half*)smem;
                const int jl = ccl >> 1;  // 0..127
                gt[(size_t)r0l * 136 + jl]       = __float2half_rn((v0 * sigm(v0)) * v1);
                gt[(size_t)(r0l + 8) * 136 + jl] = __float2half_rn((v2 * sigm(v2)) * v3);
            }
        }
    }
    if (EPI == 2) {
        __syncthreads();
        const long half = N >> 1;
#pragma unroll
        for (int i = 0; i < 4; ++i) {
            const int c = tid + i * 512;
            const int row = c >> 4, ch = c & 15;
            *(uint4*)(Ch + (bm + row) * half + (bn >> 1) + ch * 8) =
                *(uint4*)(smem + (size_t)row * 272 + ch * 16);
        }
    }
}

// ======================= fp16 GEMM (narrow: 128x128, 256 thr) ================
#define STG256 20480
#define SM256  81920

template <int EPI>
__global__ void __launch_bounds__(256, 2) hgemm256(
    const __half* __restrict__ Ap, const __half* __restrict__ Bp,
    const float* __restrict__ bias, float* __restrict__ Cf,
    int N, int K)
{
    extern __shared__ char smem[];
    const uint32_t sbase = smem_u32(smem);
    const int tid  = threadIdx.x;
    const int wid  = tid >> 5, lane = tid & 31;
    const long bm  = (long)blockIdx.y * 128;
    const long bn  = (long)blockIdx.x * 128;
    const int  wm  = wid >> 2, wn = wid & 3;
    const long kb  = (long)K * 2;

    const char* baseA = (const char*)Ap + bm * kb;
    const char* baseB = (const char*)Bp + bn * kb;
    const int lrow0 = tid >> 2, lcol = tid & 3;

    auto load_stage = [&](int kt, int buf) {
        const uint32_t so = sbase + buf * STG256;
        const long gk = (long)kt * 64 + lcol * 16;
#pragma unroll
        for (int c = 0; c < 2; ++c) {
            const int row = lrow0 + c * 64;
            asm volatile("cp.async.cg.shared.global [%0], [%1], 16;"
                :: "r"(so + row * RSTR + lcol * 16), "l"(baseA + (long)row * kb + gk));
            asm volatile("cp.async.cg.shared.global [%0], [%1], 16;"
                :: "r"(so + A512 + row * RSTR + lcol * 16), "l"(baseB + (long)row * kb + gk));
        }
        asm volatile("cp.async.commit_group;" ::: "memory");
    };

    const uint32_t g  = lane >> 3, li = lane & 7;
    const uint32_t aRow = wm * 64 + ((g & 1) << 3) + li;
    const uint32_t aCol = (g >> 1) << 4;
    const uint32_t bRow = wn * 32 + ((g >> 1) << 3) + li;
    const uint32_t bCol = (g & 1) << 4;

    float acc[4][4][4];
#pragma unroll
    for (int i = 0; i < 4; ++i)
#pragma unroll
        for (int j = 0; j < 4; ++j)
#pragma unroll
            for (int q = 0; q < 4; ++q) acc[i][j][q] = 0.f;

    const int nk = K >> 5;
    load_stage(0, 0);
    if (nk > 1) load_stage(1, 1);
    if (nk > 2) load_stage(2, 2);

    for (int kt = 0; kt < nk; ++kt) {
        if (kt <= nk - 3)      asm volatile("cp.async.wait_group 2;" ::: "memory");
        else if (kt == nk - 2) asm volatile("cp.async.wait_group 1;" ::: "memory");
        else                   asm volatile("cp.async.wait_group 0;" ::: "memory");
        __syncthreads();
        if (kt + 3 < nk) load_stage(kt + 3, (kt + 3) & 3);

        const uint32_t so = sbase + (kt & 3) * STG256;
#pragma unroll
        for (int kk = 0; kk < 2; ++kk) {
            uint32_t ah[4][4], bh[4][2];
#pragma unroll
            for (int mt = 0; mt < 4; ++mt)
                ldx4(ah[mt], so + (aRow + mt * 16) * RSTR + kk * 32 + aCol);
#pragma unroll
            for (int p = 0; p < 2; ++p) {
                uint32_t r[4];
                ldx4(r, so + A512 + (bRow + p * 16) * RSTR + kk * 32 + bCol);
                bh[2*p][0] = r[0]; bh[2*p][1] = r[1];
                bh[2*p+1][0] = r[2]; bh[2*p+1][1] = r[3];
            }
#pragma unroll
            for (int mt = 0; mt < 4; ++mt)
#pragma unroll
                for (int nt = 0; nt < 4; ++nt)
                    mma_fp16(acc[mt][nt], ah[mt], bh[nt]);
        }
    }

    if (EPI == 1) __syncthreads();

#pragma unroll
    for (int mt = 0; mt < 4; ++mt) {
        const long r0 = bm + wm * 64 + mt * 16 + (lane >> 2);
        const int  r0l = wm * 64 + mt * 16 + (lane >> 2);
#pragma unroll
        for (int nt = 0; nt < 4; ++nt) {
            const int  ccl = wn * 32 + nt * 8 + (lane & 3) * 2;
            const long cc  = bn + ccl;
            const float2 bv = *(const float2*)(bias + cc);
            float v0 = acc[mt][nt][0] + bv.x, v1 = acc[mt][nt][1] + bv.y;
            float v2 = acc[mt][nt][2] + bv.x, v3 = acc[mt][nt][3] + bv.y;
            if (EPI == 0) {
                *(float2*)(Cf + r0 * N + cc)       = make_float2(v0, v1);
                *(float2*)(Cf + (r0 + 8) * N + cc) = make_float2(v2, v3);
            } else {  // score -> smem tile, 272B row stride
                float* st = (float*)smem;
                const int jl = ccl >> 1;  // 0..63
                st[(size_t)r0l * 68 + jl]       = sigm(v0) * sigm(v1);
                st[(size_t)(r0l + 8) * 68 + jl] = sigm(v2) * sigm(v3);
            }
        }
    }
    if (EPI == 1) {
        __syncthreads();
        const long half = N >> 1;
#pragma unroll
        for (int i = 0; i < 8; ++i) {
            const int c = tid + i * 256;
            const int row = c >> 4, ch = c & 15;
            *(uint4*)(Cf + (bm + row) * half + (bn >> 1) + ch * 4) =
                *(uint4*)(smem + (size_t)row * 272 + ch * 16);
        }
    }
}

// ======================= weight transpose -> fp16 =======================
__global__ void tsplit_kernel(const float* __restrict__ W,
                              __half* __restrict__ th, int K, int N,
                              int mode, int rowoff)
{
    __shared__ float t[32][33];
    const int k0 = blockIdx.y * 32, n0 = blockIdx.x * 32;
    const int tx = threadIdx.x, ty = threadIdx.y;
#pragma unroll
    for (int i = ty; i < 32; i += 8)
        t[i][tx] = W[(long)(k0 + i) * N + n0 + tx];
    __syncthreads();
#pragma unroll
    for (int i = ty; i < 32; i += 8) {
        const int n = n0 + i;
        long row;
        if (mode == 0)      row = rowoff + n;
        else if (mode == 1) row = 2 * (long)n + rowoff;
        else                row = (n < (N >> 1)) ? 2 * (long)n : 2 * (long)(n - (N >> 1)) + 1;
        th[row * (long)K + (k0 + tx)] = __float2half_rn(t[tx][i]);
    }
}

// ======================= x -> fp16 =======================
__global__ void cvt_kernel(const float* __restrict__ x, __half* __restrict__ h, long n4)
{
    long i = (long)blockIdx.x * blockDim.x + threadIdx.x;
    if (i >= n4) return;
    float4 v = ((const float4*)x)[i];
    ((uint2*)h)[i] = make_uint2(
        pack2(__float2half_rn(v.x), __float2half_rn(v.y)),
        pack2(__float2half_rn(v.z), __float2half_rn(v.w)));
}

__global__ void bqk_kernel(const float* __restrict__ Qb, const float* __restrict__ Kb,
                           float* __restrict__ b)
{
    int i = threadIdx.x;  // 256
    b[i] = (i & 1) ? Kb[i >> 1] : Qb[i >> 1];
}

__global__ void bpj_kernel(const float* __restrict__ pb, float* __restrict__ b)
{
    int i = blockIdx.x * blockDim.x + threadIdx.x;  // 2048
    b[i] = pb[(i >> 1) + (i & 1) * DH];
}

// ============== EMA scan + mean/clip * V -> fp16 (warp-only, no barriers) =====
#define EMA_CHUNK 128
#define EMA_WARM  256
__global__ void __launch_bounds__(32) ema_fused(
    const float* __restrict__ sc, const float* __restrict__ V,
    __half* __restrict__ xch)
{
    const int b  = blockIdx.y;
    const int t0 = blockIdx.x * EMA_CHUNK;
    const int lt = threadIdx.x;  // 32 threads, each owns 4 f-lanes
    const float4* sb = (const float4*)(sc + ((long)b * SEQ) * FDIM) + lt;
    const float4* Vb = (const float4*)(V  + ((long)b * SEQ) * FDIM) + lt;
    __half*       xb = xch + ((long)b * SEQ) * FDIM + lt * 4;

    auto emit = [&](int t, float4 p) {
        float s = p.x + p.y + p.z + p.w;
#pragma unroll
        for (int o = 16; o; o >>= 1) s += __shfl_xor_sync(0xffffffffu, s, o);
        const float inv = 1.0f / fmaxf(s * (1.0f / 128.0f), 1e-6f);
        float4 v = Vb[(long)t * 32];
        float c0 = fminf(fmaxf(p.x * inv, -5.0f), 5.0f) * v.x;
        float c1 = fminf(fmaxf(p.y * inv, -5.0f), 5.0f) * v.y;
        float c2 = fminf(fmaxf(p.z * inv, -5.0f), 5.0f) * v.z;
        float c3 = fminf(fmaxf(p.w * inv, -5.0f), 5.0f) * v.w;
        *(uint2*)(xb + (long)t * FDIM) = make_uint2(
            pack2(__float2half_rn(c0), __float2half_rn(c1)),
            pack2(__float2half_rn(c2), __float2half_rn(c3)));
    };

    int t = t0 - EMA_WARM;
    float4 prev;
    if (t <= 0) {
        prev = sb[0];
        if (t0 == 0) emit(0, prev);
        t = 1;
    } else {
        prev = make_float4(0.f, 0.f, 0.f, 0.f);
    }
    const int tend = t0 + EMA_CHUNK;
    for (; t < tend; ++t) {
        float4 s = sb[(long)t * 32];
        prev.x = 0.15f * s.x + 0.85f * prev.x;
        prev.y = 0.15f * s.y + 0.85f * prev.y;
        prev.z = 0.15f * s.z + 0.85f * prev.z;
        prev.w = 0.15f * s.w + 0.85f * prev.w;
        if (t >= t0) emit(t, prev);
    }
}

// ======================= residual + LayerNorm =======================
__global__ void __launch_bounds__(256) ln_kernel(
    const float* __restrict__ o2, const float* __restrict__ x,
    const float* __restrict__ gamma, const float* __restrict__ beta,
    float* __restrict__ y)
{
    __shared__ float ws[8];
    const long row = blockIdx.x;
    const int  tid = threadIdx.x;
    const float* pr = o2 + row * DDIM;
    const float* px = x  + row * DDIM;
    const int c0 = tid * 4;
    const int c1 = 1024 + tid * 4;

    float4 a0 = *(const float4*)(pr + c0), r0 = *(const float4*)(px + c0);
    float4 a1 = *(const float4*)(pr + c1), r1 = *(const float4*)(px + c1);
    float h[8] = { a0.x + r0.x, a0.y + r0.y, a0.z + r0.z, a0.w + r0.w,
                   a1.x + r1.x, a1.y + r1.y, a1.z + r1.z, a1.w + r1.w };

    float s = 0.f;
#pragma unroll
    for (int i = 0; i < 8; ++i) s += h[i];
#pragma unroll
    for (int o = 16; o; o >>= 1) s += __shfl_xor_sync(0xffffffffu, s, o);
    if ((tid & 31) == 0) ws[tid >> 5] = s;
    __syncthreads();
    float tot = 0.f;
#pragma unroll
    for (int i = 0; i < 8; ++i) tot += ws[i];
    const float mu = tot * (1.0f / 2048.0f);
    __syncthreads();

    float sq = 0.f;
#pragma unroll
    for (int i = 0; i < 8; ++i) { float d = h[i] - mu; sq += d * d; }
#pragma unroll
    for (int o = 16; o; o >>= 1) sq += __shfl_xor_sync(0xffffffffu, sq, o);
    if ((tid & 31) == 0) ws[tid >> 5] = sq;
    __syncthreads();
    float tot2 = 0.f;
#pragma unroll
    for (int i = 0; i < 8; ++i) tot2 += ws[i];
    const float inv = rsqrtf(tot2 * (1.0f / 2048.0f) + 1e-5f);

    float4 g0 = *(const float4*)(gamma + c0), g1 = *(const float4*)(gamma + c1);
    float4 b0 = *(const float4*)(beta  + c0), b1 = *(const float4*)(beta  + c1);
    float4 y0, y1;
    y0.x = (h[0] - mu) * inv * g0.x + b0.x;
    y0.y = (h[1] - mu) * inv * g0.y + b0.y;
    y0.z = (h[2] - mu) * inv * g0.z + b0.z;
    y0.w = (h[3] - mu) * inv * g0.w + b0.w;
    y1.x = (h[4] - mu) * inv * g1.x + b1.x;
    y1.y = (h[5] - mu) * inv * g1.y + b1.y;
    y1.z = (h[6] - mu) * inv * g1.z + b1.z;
    y1.w = (h[7] - mu) * inv * g1.w + b1.w;
    *(float4*)(y + row * DDIM + c0) = y0;
    *(float4*)(y + row * DDIM + c1) = y1;
}

// ======================= launch =======================
extern "C" void kernel_launch(void* const* d_in, const int* in_sizes, int n_in,
                              void* d_out, int out_size)
{
    const float* x      = (const float*)d_in[0];
    const float* Qw     = (const float*)d_in[1];
    const float* Qb     = (const float*)d_in[2];
    const float* Kw     = (const float*)d_in[3];
    const float* Kb     = (const float*)d_in[4];
    const float* low    = (const float*)d_in[5];
    const float* lob    = (const float*)d_in[6];
    const float* lopw   = (const float*)d_in[7];
    const float* lopb   = (const float*)d_in[8];
    const float* projw  = (const float*)d_in[9];
    const float* projb  = (const float*)d_in[10];
    const float* Ow     = (const float*)d_in[11];
    const float* Ob     = (const float*)d_in[12];
    const float* gamma  = (const float*)d_in[13];
    const float* beta   = (const float*)d_in[14];
    float* out = (float*)d_out;

    float *sc, *V, *o2, *bqk, *bpj;
    __half *xh, *Hh, *xch, *gh;
    __half *wqk, *wlo, *wlp, *wpj, *wo;
    cudaGetSymbolAddress((void**)&sc,  g_sc);
    cudaGetSymbolAddress((void**)&V,   g_V);
    cudaGetSymbolAddress((void**)&o2,  g_o2);
    cudaGetSymbolAddress((void**)&bqk, g_bqk);
    cudaGetSymbolAddress((void**)&bpj, g_bpj);
    cudaGetSymbolAddress((void**)&xh,  g_xh);
    cudaGetSymbolAddress((void**)&Hh,  g_Hh);
    cudaGetSymbolAddress((void**)&xch, g_xch);
    cudaGetSymbolAddress((void**)&gh,  g_gh);
    cudaGetSymbolAddress((void**)&wqk, g_wqk);
    cudaGetSymbolAddress((void**)&wlo, g_wlo);
    cudaGetSymbolAddress((void**)&wlp, g_wlp);
    cudaGetSymbolAddress((void**)&wpj, g_wpj);
    cudaGetSymbolAddress((void**)&wo,  g_wo);

    cudaFuncSetAttribute(hgemm512<0>, cudaFuncAttributeMaxDynamicSharedMemorySize, SM512);
    cudaFuncSetAttribute(hgemm512<1>, cudaFuncAttributeMaxDynamicSharedMemorySize, SM512);
    cudaFuncSetAttribute(hgemm512<2>, cudaFuncAttributeMaxDynamicSharedMemorySize, SM512);
    cudaFuncSetAttribute(hgemm256<0>, cudaFuncAttributeMaxDynamicSharedMemorySize, SM256);
    cudaFuncSetAttribute(hgemm256<1>, cudaFuncAttributeMaxDynamicSharedMemorySize, SM256);

    const dim3 tb32(32, 8);
    // launches 1-4: deps of H GEMM + fillers so H is the 5th launch (ncu -s 5)
    tsplit_kernel<<<dim3(DDIM/32, DDIM/32), tb32>>>(low,  wlo, DDIM, DDIM, 0, 0);  // 1
    {
        long n4 = (long)MROWS * DDIM / 4;
        cvt_kernel<<<(unsigned)((n4 + 255) / 256), 256>>>(x, xh, n4);              // 2
    }
    bqk_kernel<<<1, 256>>>(Qb, Kb, bqk);                                           // 3
    tsplit_kernel<<<dim3(FDIM/32, DDIM/32), tb32>>>(Qw, wqk, DDIM, FDIM, 1, 0);    // 4
    // H = gelu(x @ lo_proj_w + b) -> fp16   [launch 5 — profiled]
    hgemm512<1><<<dim3(DDIM/256, MROWS/128), 512, SM512>>>(xh, wlo, lob, nullptr, Hh, DDIM, DDIM);
    // remaining weight prep
    tsplit_kernel<<<dim3(FDIM/32, DDIM/32), tb32>>>(Kw, wqk, DDIM, FDIM, 1, 1);
    tsplit_kernel<<<dim3(FDIM/32, DDIM/32), tb32>>>(lopw, wlp, DDIM, FDIM, 0, 0);
    tsplit_kernel<<<dim3(DDIM/32, FDIM/32), tb32>>>(projw,wpj, FDIM, DDIM, 2, 0);
    bpj_kernel<<<DDIM/256, 256>>>(projb, bpj);
    tsplit_kernel<<<dim3(DDIM/32, DH/32),   tb32>>>(Ow, wo, DH, DDIM, 0, 0);
    // sc = sigm(q)*sigm(k), fused in qk GEMM (staged coalesced stores)
    hgemm256<1><<<dim3(2, MROWS/128), 256, SM256>>>(xh, wqk, bqk, sc, 256, DDIM);
    // V = H @ lo_p_w + b
    hgemm256<0><<<dim3(1, MROWS/128), 256, SM256>>>(Hh, wlp, lopb, V, FDIM, DDIM);
    // EMA + mean/clip * V -> xch (warp-only fused)
    ema_fused<<<dim3(SEQ / EMA_CHUNK, NBATCH), 32>>>(sc, V, xch);
    // gh = silu(a)*b, fused in o1 GEMM (staged coalesced stores)
    hgemm512<2><<<dim3(DDIM/256, MROWS/128), 512, SM512>>>(xch, wpj, bpj, nullptr, gh, DDIM, FDIM);
    // o2 = g @ O_w + b
    hgemm512<0><<<dim3(DDIM/256, MROWS/128), 512, SM512>>>(gh, wo, Ob, o2, nullptr, DDIM, DH);
    // residual + LN
    ln_kernel<<<MROWS, 256>>>(o2, x, gamma, beta, out);
}

// round 13
// speedup vs baseline: 1.1893x; 1.1458x over previous
#include <cuda_runtime.h>
#include <cuda_fp16.h>
#include <cstdint>

// Problem dims
#define MROWS 16384   // B*S
#define DDIM  2048
#define FDIM  128
#define DH    1024
#define SEQ   4096
#define NBATCH 4

// ======================= scratch (static, no allocs) =======================
__device__ __align__(256) float g_qk[(size_t)MROWS * 256];
__device__ __align__(256) float g_sc[(size_t)MROWS * FDIM];
__device__ __align__(256) float g_em[(size_t)MROWS * FDIM];
__device__ __align__(256) float g_V [(size_t)MROWS * FDIM];
__device__ __align__(256) float g_o1[(size_t)MROWS * DDIM];
__device__ __align__(256) float g_o2[(size_t)MROWS * DDIM];
__device__ __align__(256) float g_bqk[256];
// fp16 activations
__device__ __align__(256) __half g_xh [(size_t)MROWS * DDIM];
__device__ __align__(256) __half g_Hh [(size_t)MROWS * DDIM];
__device__ __align__(256) __half g_xch[(size_t)MROWS * FDIM];
__device__ __align__(256) __half g_gh [(size_t)MROWS * DH];
// fp16 transposed weights W^T [N, K] (K contiguous)
__device__ __align__(256) __half g_wqk[(size_t)256 * DDIM];
__device__ __align__(256) __half g_wlo[(size_t)DDIM * DDIM];
__device__ __align__(256) __half g_wlp[(size_t)FDIM * DDIM];
__device__ __align__(256) __half g_wpj[(size_t)DDIM * FDIM];
__device__ __align__(256) __half g_wo [(size_t)DDIM * DH];

// ======================= helpers =======================
__device__ __forceinline__ uint32_t smem_u32(const void* p) {
    uint32_t a;
    asm("{ .reg .u64 t; cvta.to.shared.u64 t, %1; cvt.u32.u64 %0, t; }" : "=r"(a) : "l"(p));
    return a;
}
__device__ __forceinline__ void ldx4(uint32_t* r, uint32_t addr) {
    asm volatile("ldmatrix.sync.aligned.m8n8.x4.shared.b16 {%0,%1,%2,%3}, [%4];"
        : "=r"(r[0]), "=r"(r[1]), "=r"(r[2]), "=r"(r[3]) : "r"(addr));
}
__device__ __forceinline__ void mma_fp16(float* c, const uint32_t* a, const uint32_t* b) {
    asm volatile("mma.sync.aligned.m16n8k16.row.col.f32.f16.f16.f32 "
        "{%0,%1,%2,%3}, {%4,%5,%6,%7}, {%8,%9}, {%0,%1,%2,%3};"
        : "+f"(c[0]), "+f"(c[1]), "+f"(c[2]), "+f"(c[3])
        : "r"(a[0]), "r"(a[1]), "r"(a[2]), "r"(a[3]), "r"(b[0]), "r"(b[1]));
}
__device__ __forceinline__ float sigm(float x) { return 1.0f / (1.0f + __expf(-x)); }
__device__ __forceinline__ float gelu_f(float x) {
    float z  = 0.7978845608028654f * (x + 0.044715f * x * x * x);
    float az = fabsf(z);
    float e  = __expf(-2.0f * az);
    float t  = (1.0f - e) / (1.0f + e);
    t = copysignf(t, z);
    return 0.5f * x * (1.0f + t);
}
__device__ __forceinline__ uint32_t pack2(__half a, __half b) {
    return (uint32_t)__half_as_ushort(a) | ((uint32_t)__half_as_ushort(b) << 16);
}

// BK=64: 128B data per row + 16B pad = 144B row stride.
// 144B = 36 words -> +4 banks per row -> 8 ldmatrix rows hit all 32 banks: conflict-free.
#define RSTR2 144

// ======================= fp16 HMMA GEMM (wide: 128x256, 512 thr) =============
// C[M,N] = A[M,K](fp16) @ B^T[N,K](fp16). BK=64, 3-stage cp.async pipeline.
// 16 warps (2x8), warp tile 64x32.
// EPI 0: Cf = acc + bias (f32). EPI 1: gelu(acc+bias) -> Ch (fp16).
#define AT512  18432          // 128*RSTR2
#define STG512 55296          // (128+256)*RSTR2
#define SM512  165888         // 3 stages

template <int EPI>
__global__ void __launch_bounds__(512, 1) hgemm512(
    const __half* __restrict__ Ap, const __half* __restrict__ Bp,
    const float* __restrict__ bias,
    float* __restrict__ Cf, __half* __restrict__ Ch,
    int N, int K)
{
    extern __shared__ char smem[];
    const uint32_t sbase = smem_u32(smem);
    const int tid  = threadIdx.x;
    const int wid  = tid >> 5, lane = tid & 31;
    const long bm  = (long)blockIdx.y * 128;
    const long bn  = (long)blockIdx.x * 256;
    const int  wm  = wid >> 3, wn = wid & 7;
    const long kb  = (long)K * 2;

    const char* baseA = (const char*)Ap + bm * kb;
    const char* baseB = (const char*)Bp + bn * kb;
    const int crow = tid >> 3, ccol = tid & 7;   // chunk coords: 8x16B = 128B row

    auto load_stage = [&](int kt, int slot) {
        const uint32_t so = sbase + slot * STG512;
        const long gk = (long)kt * 128 + ccol * 16;
        // A: 128 rows, 2 chunks/thread
#pragma unroll
        for (int c = 0; c < 2; ++c) {
            const int row = crow + c * 64;
            asm volatile("cp.async.cg.shared.global [%0], [%1], 16;"
                :: "r"(so + row * RSTR2 + ccol * 16), "l"(baseA + (long)row * kb + gk));
        }
        // B: 256 rows, 4 chunks/thread
#pragma unroll
        for (int c = 0; c < 4; ++c) {
            const int row = crow + c * 64;
            asm volatile("cp.async.cg.shared.global [%0], [%1], 16;"
                :: "r"(so + AT512 + row * RSTR2 + ccol * 16), "l"(baseB + (long)row * kb + gk));
        }
        asm volatile("cp.async.commit_group;" ::: "memory");
    };

    const uint32_t g  = lane >> 3, li = lane & 7;
    const uint32_t aRow = wm * 64 + ((g & 1) << 3) + li;
    const uint32_t aCol = (g >> 1) << 4;
    const uint32_t bRow = wn * 32 + ((g >> 1) << 3) + li;
    const uint32_t bCol = (g & 1) << 4;

    float acc[4][4][4];
#pragma unroll
    for (int i = 0; i < 4; ++i)
#pragma unroll
        for (int j = 0; j < 4; ++j)
#pragma unroll
            for (int q = 0; q < 4; ++q) acc[i][j][q] = 0.f;

    const int nk = K >> 6;
    load_stage(0, 0);
    if (nk > 1) load_stage(1, 1);

    for (int kt = 0; kt < nk; ++kt) {
        if (kt + 1 < nk) asm volatile("cp.async.wait_group 1;" ::: "memory");
        else             asm volatile("cp.async.wait_group 0;" ::: "memory");
        __syncthreads();
        if (kt + 2 < nk) load_stage(kt + 2, (kt + 2) % 3);

        const uint32_t so = sbase + (kt % 3) * STG512;
#pragma unroll
        for (int kk = 0; kk < 4; ++kk) {
            uint32_t ah[4][4], bh[4][2];
#pragma unroll
            for (int mt = 0; mt < 4; ++mt)
                ldx4(ah[mt], so + (aRow + mt * 16) * RSTR2 + kk * 32 + aCol);
#pragma unroll
            for (int p = 0; p < 2; ++p) {
                uint32_t r[4];
                ldx4(r, so + AT512 + (bRow + p * 16) * RSTR2 + kk * 32 + bCol);
                bh[2*p][0] = r[0]; bh[2*p][1] = r[1];
                bh[2*p+1][0] = r[2]; bh[2*p+1][1] = r[3];
            }
#pragma unroll
            for (int mt = 0; mt < 4; ++mt)
#pragma unroll
                for (int nt = 0; nt < 4; ++nt)
                    mma_fp16(acc[mt][nt], ah[mt], bh[nt]);
        }
    }

#pragma unroll
    for (int mt = 0; mt < 4; ++mt) {
        const long r0 = bm + wm * 64 + mt * 16 + (lane >> 2);
#pragma unroll
        for (int nt = 0; nt < 4; ++nt) {
            const long cc = bn + wn * 32 + nt * 8 + (lane & 3) * 2;
            const float2 bv = *(const float2*)(bias + cc);
            float v0 = acc[mt][nt][0] + bv.x, v1 = acc[mt][nt][1] + bv.y;
            float v2 = acc[mt][nt][2] + bv.x, v3 = acc[mt][nt][3] + bv.y;
            if (EPI == 0) {
                *(float2*)(Cf + r0 * N + cc)       = make_float2(v0, v1);
                *(float2*)(Cf + (r0 + 8) * N + cc) = make_float2(v2, v3);
            } else {
                *(uint32_t*)(Ch + r0 * N + cc) =
                    pack2(__float2half_rn(gelu_f(v0)), __float2half_rn(gelu_f(v1)));
                *(uint32_t*)(Ch + (r0 + 8) * N + cc) =
                    pack2(__float2half_rn(gelu_f(v2)), __float2half_rn(gelu_f(v3)));
            }
        }
    }
}

// ======================= fp16 GEMM (narrow: 128x128, 256 thr) ================
// BK=64, 3-stage. EPI 0 only: Cf = acc + bias.
#define STG256 36864          // 2*128*RSTR2
#define SM256  110592         // 3 stages

__global__ void __launch_bounds__(256, 1) hgemm256(
    const __half* __restrict__ Ap, const __half* __restrict__ Bp,
    const float* __restrict__ bias, float* __restrict__ Cf,
    int N, int K)
{
    extern __shared__ char smem[];
    const uint32_t sbase = smem_u32(smem);
    const int tid  = threadIdx.x;
    const int wid  = tid >> 5, lane = tid & 31;
    const long bm  = (long)blockIdx.y * 128;
    const long bn  = (long)blockIdx.x * 128;
    const int  wm  = wid >> 2, wn = wid & 3;
    const long kb  = (long)K * 2;

    const char* baseA = (const char*)Ap + bm * kb;
    const char* baseB = (const char*)Bp + bn * kb;
    const int crow = tid >> 3, ccol = tid & 7;   // 32 rows per 256 thr

    auto load_stage = [&](int kt, int slot) {
        const uint32_t so = sbase + slot * STG256;
        const long gk = (long)kt * 128 + ccol * 16;
#pragma unroll
        for (int c = 0; c < 4; ++c) {
            const int row = crow + c * 32;
            asm volatile("cp.async.cg.shared.global [%0], [%1], 16;"
                :: "r"(so + row * RSTR2 + ccol * 16), "l"(baseA + (long)row * kb + gk));
            asm volatile("cp.async.cg.shared.global [%0], [%1], 16;"
                :: "r"(so + AT512 + row * RSTR2 + ccol * 16), "l"(baseB + (long)row * kb + gk));
        }
        asm volatile("cp.async.commit_group;" ::: "memory");
    };

    const uint32_t g  = lane >> 3, li = lane & 7;
    const uint32_t aRow = wm * 64 + ((g & 1) << 3) + li;
    const uint32_t aCol = (g >> 1) << 4;
    const uint32_t bRow = wn * 32 + ((g >> 1) << 3) + li;
    const uint32_t bCol = (g & 1) << 4;

    float acc[4][4][4];
#pragma unroll
    for (int i = 0; i < 4; ++i)
#pragma unroll
        for (int j = 0; j < 4; ++j)
#pragma unroll
            for (int q = 0; q < 4; ++q) acc[i][j][q] = 0.f;

    const int nk = K >> 6;
    load_stage(0, 0);
    if (nk > 1) load_stage(1, 1);

    for (int kt = 0; kt < nk; ++kt) {
        if (kt + 1 < nk) asm volatile("cp.async.wait_group 1;" ::: "memory");
        else             asm volatile("cp.async.wait_group 0;" ::: "memory");
        __syncthreads();
        if (kt + 2 < nk) load_stage(kt + 2, (kt + 2) % 3);

        const uint32_t so = sbase + (kt % 3) * STG256;
#pragma unroll
        for (int kk = 0; kk < 4; ++kk) {
            uint32_t ah[4][4], bh[4][2];
#pragma unroll
            for (int mt = 0; mt < 4; ++mt)
                ldx4(ah[mt], so + (aRow + mt * 16) * RSTR2 + kk * 32 + aCol);
#pragma unroll
            for (int p = 0; p < 2; ++p) {
                uint32_t r[4];
                ldx4(r, so + AT512 + (bRow + p * 16) * RSTR2 + kk * 32 + bCol);
                bh[2*p][0] = r[0]; bh[2*p][1] = r[1];
                bh[2*p+1][0] = r[2]; bh[2*p+1][1] = r[3];
            }
#pragma unroll
            for (int mt = 0; mt < 4; ++mt)
#pragma unroll
                for (int nt = 0; nt < 4; ++nt)
                    mma_fp16(acc[mt][nt], ah[mt], bh[nt]);
        }
    }

#pragma unroll
    for (int mt = 0; mt < 4; ++mt) {
        const long r0 = bm + wm * 64 + mt * 16 + (lane >> 2);
#pragma unroll
        for (int nt = 0; nt < 4; ++nt) {
            const long cc = bn + wn * 32 + nt * 8 + (lane & 3) * 2;
            const float2 bv = *(const float2*)(bias + cc);
            *(float2*)(Cf + r0 * N + cc) =
                make_float2(acc[mt][nt][0] + bv.x, acc[mt][nt][1] + bv.y);
            *(float2*)(Cf + (r0 + 8) * N + cc) =
                make_float2(acc[mt][nt][2] + bv.x, acc[mt][nt][3] + bv.y);
        }
    }
}

// ======================= weight transpose -> fp16 =======================
__global__ void tsplit_kernel(const float* __restrict__ W,
                              __half* __restrict__ th, int K, int N, int rowoff)
{
    __shared__ float t[32][33];
    const int k0 = blockIdx.y * 32, n0 = blockIdx.x * 32;
    const int tx = threadIdx.x, ty = threadIdx.y;
#pragma unroll
    for (int i = ty; i < 32; i += 8)
        t[i][tx] = W[(long)(k0 + i) * N + n0 + tx];
    __syncthreads();
#pragma unroll
    for (int i = ty; i < 32; i += 8) {
        const long n = n0 + i, k = k0 + tx;
        th[(rowoff + n) * (long)K + k] = __float2half_rn(t[tx][i]);
    }
}

// ======================= x -> fp16 =======================
__global__ void cvt_kernel(const float* __restrict__ x, __half* __restrict__ h, long n4)
{
    long i = (long)blockIdx.x * blockDim.x + threadIdx.x;
    if (i >= n4) return;
    float4 v = ((const float4*)x)[i];
    ((uint2*)h)[i] = make_uint2(
        pack2(__float2half_rn(v.x), __float2half_rn(v.y)),
        pack2(__float2half_rn(v.z), __float2half_rn(v.w)));
}

__global__ void bqk_kernel(const float* __restrict__ Qb, const float* __restrict__ Kb,
                           float* __restrict__ b)
{
    int i = threadIdx.x;
    b[i] = (i < 128) ? Qb[i] : Kb[i - 128];
}

// ======================= score = sigmoid(q)*sigmoid(k) =======================
__global__ void score_kernel(const float* __restrict__ qk, float* __restrict__ s)
{
    long i = (long)blockIdx.x * blockDim.x + threadIdx.x;
    long m = i >> 7;
    int  f = (int)(i & 127);
    s[i] = sigm(qk[m * 256 + f]) * sigm(qk[m * 256 + 128 + f]);
}

// ======================= chunked EMA scan over time =======================
#define EMA_CHUNK 128
#define EMA_WARM  256
__global__ void ema_kernel(const float* __restrict__ sc, float* __restrict__ ema)
{
    const int b  = blockIdx.y;
    const int t0 = blockIdx.x * EMA_CHUNK;
    const int f  = threadIdx.x;
    const float* sb = sc  + ((long)b * SEQ) * FDIM + f;
    float*       eb = ema + ((long)b * SEQ) * FDIM + f;

    int   t = t0 - EMA_WARM;
    float prev;
    if (t <= 0) {
        prev = sb[0];
        if (t0 == 0) eb[0] = prev;
        t = 1;
    } else {
        prev = 0.0f;
    }
    const int tend = t0 + EMA_CHUNK;
    for (; t < tend; ++t) {
        float s = sb[(long)t * FDIM];
        prev = 0.15f * s + 0.85f * prev;
        if (t >= t0) eb[(long)t * FDIM] = prev;
    }
}

// ======================= mean/clip * V -> fp16 =======================
__global__ void normclip_kernel(const float* __restrict__ ema, const float* __restrict__ V,
                                __half* __restrict__ xh)
{
    const long row = blockIdx.x;
    const int  f   = threadIdx.x;  // 128
    float e = ema[row * FDIM + f];
    float s = e;
#pragma unroll
    for (int o = 16; o; o >>= 1) s += __shfl_xor_sync(0xffffffffu, s, o);
    __shared__ float ws[4];
    if ((f & 31) == 0) ws[f >> 5] = s;
    __syncthreads();
    float tot = ws[0] + ws[1] + ws[2] + ws[3];
    float denom = fmaxf(tot * (1.0f / 128.0f), 1e-6f);
    float c = e / denom;
    c = fminf(fmaxf(c, -5.0f), 5.0f);
    xh[row * FDIM + f] = __float2half_rn(c * V[row * FDIM + f]);
}

// ======================= SwiGLU gate -> fp16 =======================
__global__ void gate_kernel(const float* __restrict__ o1, __half* __restrict__ gh)
{
    long i = (long)blockIdx.x * blockDim.x + threadIdx.x;
    long m = i >> 10;
    int  j = (int)(i & 1023);
    float a  = o1[m * DDIM + j];
    float bv = o1[m * DDIM + j + DH];
    gh[i] = __float2half_rn((a * sigm(a)) * bv);
}

// ======================= residual + LayerNorm =======================
__global__ void __launch_bounds__(256) ln_kernel(
    const float* __restrict__ o2, const float* __restrict__ x,
    const float* __restrict__ gamma, const float* __restrict__ beta,
    float* __restrict__ y)
{
    __shared__ float ws[8];
    const long row = blockIdx.x;
    const int  tid = threadIdx.x;
    const float* pr = o2 + row * DDIM;
    const float* px = x  + row * DDIM;
    const int c0 = tid * 4;
    const int c1 = 1024 + tid * 4;

    float4 a0 = *(const float4*)(pr + c0), r0 = *(const float4*)(px + c0);
    float4 a1 = *(const float4*)(pr + c1), r1 = *(const float4*)(px + c1);
    float h[8] = { a0.x + r0.x, a0.y + r0.y, a0.z + r0.z, a0.w + r0.w,
                   a1.x + r1.x, a1.y + r1.y, a1.z + r1.z, a1.w + r1.w };

    float s = 0.f;
#pragma unroll
    for (int i = 0; i < 8; ++i) s += h[i];
#pragma unroll
    for (int o = 16; o; o >>= 1) s += __shfl_xor_sync(0xffffffffu, s, o);
    if ((tid & 31) == 0) ws[tid >> 5] = s;
    __syncthreads();
    float tot = 0.f;
#pragma unroll
    for (int i = 0; i < 8; ++i) tot += ws[i];
    const float mu = tot * (1.0f / 2048.0f);
    __syncthreads();

    float sq = 0.f;
#pragma unroll
    for (int i = 0; i < 8; ++i) { float d = h[i] - mu; sq += d * d; }
#pragma unroll
    for (int o = 16; o; o >>= 1) sq += __shfl_xor_sync(0xffffffffu, sq, o);
    if ((tid & 31) == 0) ws[tid >> 5] = sq;
    __syncthreads();
    float tot2 = 0.f;
#pragma unroll
    for (int i = 0; i < 8; ++i) tot2 += ws[i];
    const float inv = rsqrtf(tot2 * (1.0f / 2048.0f) + 1e-5f);

    float4 g0 = *(const float4*)(gamma + c0), g1 = *(const float4*)(gamma + c1);
    float4 b0 = *(const float4*)(beta  + c0), b1 = *(const float4*)(beta  + c1);
    float4 y0, y1;
    y0.x = (h[0] - mu) * inv * g0.x + b0.x;
    y0.y = (h[1] - mu) * inv * g0.y + b0.y;
    y0.z = (h[2] - mu) * inv * g0.z + b0.z;
    y0.w = (h[3] - mu) * inv * g0.w + b0.w;
    y1.x = (h[4] - mu) * inv * g1.x + b1.x;
    y1.y = (h[5] - mu) * inv * g1.y + b1.y;
    y1.z = (h[6] - mu) * inv * g1.z + b1.z;
    y1.w = (h[7] - mu) * inv * g1.w + b1.w;
    *(float4*)(y + row * DDIM + c0) = y0;
    *(float4*)(y + row * DDIM + c1) = y1;
}

// ======================= launch =======================
extern "C" void kernel_launch(void* const* d_in, const int* in_sizes, int n_in,
                              void* d_out, int out_size)
{
    const float* x      = (const float*)d_in[0];
    const float* Qw     = (const float*)d_in[1];
    const float* Qb     = (const float*)d_in[2];
    const float* Kw     = (const float*)d_in[3];
    const float* Kb     = (const float*)d_in[4];
    const float* low    = (const float*)d_in[5];
    const float* lob    = (const float*)d_in[6];
    const float* lopw   = (const float*)d_in[7];
    const float* lopb   = (const float*)d_in[8];
    const float* projw  = (const float*)d_in[9];
    const float* projb  = (const float*)d_in[10];
    const float* Ow     = (const float*)d_in[11];
    const float* Ob     = (const float*)d_in[12];
    const float* gamma  = (const float*)d_in[13];
    const float* beta   = (const float*)d_in[14];
    float* out = (float*)d_out;

    float *qk, *sc, *em, *V, *o1, *o2, *bqk;
    __half *xh, *Hh, *xch, *gh;
    __half *wqk, *wlo, *wlp, *wpj, *wo;
    cudaGetSymbolAddress((void**)&qk,  g_qk);
    cudaGetSymbolAddress((void**)&sc,  g_sc);
    cudaGetSymbolAddress((void**)&em,  g_em);
    cudaGetSymbolAddress((void**)&V,   g_V);
    cudaGetSymbolAddress((void**)&o1,  g_o1);
    cudaGetSymbolAddress((void**)&o2,  g_o2);
    cudaGetSymbolAddress((void**)&bqk, g_bqk);
    cudaGetSymbolAddress((void**)&xh,  g_xh);
    cudaGetSymbolAddress((void**)&Hh,  g_Hh);
    cudaGetSymbolAddress((void**)&xch, g_xch);
    cudaGetSymbolAddress((void**)&gh,  g_gh);
    cudaGetSymbolAddress((void**)&wqk, g_wqk);
    cudaGetSymbolAddress((void**)&wlo, g_wlo);
    cudaGetSymbolAddress((void**)&wlp, g_wlp);
    cudaGetSymbolAddress((void**)&wpj, g_wpj);
    cudaGetSymbolAddress((void**)&wo,  g_wo);

    cudaFuncSetAttribute(hgemm512<0>, cudaFuncAttributeMaxDynamicSharedMemorySize, SM512);
    cudaFuncSetAttribute(hgemm512<1>, cudaFuncAttributeMaxDynamicSharedMemorySize, SM512);
    cudaFuncSetAttribute(hgemm256,    cudaFuncAttributeMaxDynamicSharedMemorySize, SM256);

    const dim3 tb32(32, 8);
    // launches 1-5: deps of the H GEMM, so H is the 6th launch (ncu -s 5 -c 1)
    tsplit_kernel<<<dim3(DDIM/32, DDIM/32), tb32>>>(low,  wlo, DDIM, DDIM, 0);   // 1
    {
        long n4 = (long)MROWS * DDIM / 4;
        cvt_kernel<<<(unsigned)((n4 + 255) / 256), 256>>>(x, xh, n4);            // 2
    }
    bqk_kernel<<<1, 256>>>(Qb, Kb, bqk);                                         // 3
    tsplit_kernel<<<dim3(FDIM/32, DDIM/32), tb32>>>(Qw, wqk, DDIM, FDIM, 0);     // 4
    tsplit_kernel<<<dim3(FDIM/32, DDIM/32), tb32>>>(Kw, wqk, DDIM, FDIM, 128);   // 5
    // H = gelu(x @ lo_proj_w + b) -> fp16   [launch 6 — profiled]
    hgemm512<1><<<dim3(DDIM/256, MROWS/128), 512, SM512>>>(xh, wlo, lob, nullptr, Hh, DDIM, DDIM);
    // remaining weight prep
    tsplit_kernel<<<dim3(FDIM/32, DDIM/32), tb32>>>(lopw, wlp, DDIM, FDIM, 0);
    tsplit_kernel<<<dim3(DDIM/32, FDIM/32), tb32>>>(projw,wpj, FDIM, DDIM, 0);
    tsplit_kernel<<<dim3(DDIM/32, DH/32),   tb32>>>(Ow, wo, DH, DDIM, 0);
    // qk = x @ [Qw|Kw] + [Qb|Kb]
    hgemm256<<<dim3(2, MROWS/128), 256, SM256>>>(xh, wqk, bqk, qk, 256, DDIM);
    score_kernel<<<(MROWS * FDIM) / 256, 256>>>(qk, sc);
    // V = H @ lo_p_w + b
    hgemm256<<<dim3(1, MROWS/128), 256, SM256>>>(Hh, wlp, lopb, V, FDIM, DDIM);
    // EMA, norm/clip
    ema_kernel<<<dim3(SEQ / EMA_CHUNK, NBATCH), 128>>>(sc, em);
    normclip_kernel<<<MROWS, 128>>>(em, V, xch);
    // o1 = xc @ proj_w + b
    hgemm512<0><<<dim3(DDIM/256, MROWS/128), 512, SM512>>>(xch, wpj, projb, o1, nullptr, DDIM, FDIM);
    // gate
    gate_kernel<<<(MROWS * DH) / 256, 256>>>(o1, gh);
    // o2 = g @ O_w + b
    hgemm512<0><<<dim3(DDIM/256, MROWS/128), 512, SM512>>>(gh, wo, Ob, o2, nullptr, DDIM, DH);
    // residual + LN
    ln_kernel<<<MROWS, 256>>>(o2, x, gamma, beta, out);
}

// round 14
// speedup vs baseline: 1.2830x; 1.0789x over previous
#include <cuda_runtime.h>
#include <cuda_fp16.h>
#include <cstdint>

// Problem dims
#define MROWS 16384   // B*S
#define DDIM  2048
#define FDIM  128
#define DH    1024
#define SEQ   4096
#define NBATCH 4

// ======================= scratch (static, no allocs) =======================
__device__ __align__(256) float g_qk[(size_t)MROWS * 256];
__device__ __align__(256) float g_sc[(size_t)MROWS * FDIM];
__device__ __align__(256) float g_em[(size_t)MROWS * FDIM];
__device__ __align__(256) float g_V [(size_t)MROWS * FDIM];
__device__ __align__(256) float g_o2[(size_t)MROWS * DDIM];
__device__ __align__(256) float g_bqk[256];
// fp16 activations
__device__ __align__(256) __half g_xh [(size_t)MROWS * DDIM];
__device__ __align__(256) __half g_Hh [(size_t)MROWS * DDIM];
__device__ __align__(256) __half g_xch[(size_t)MROWS * FDIM];
__device__ __align__(256) __half g_o1h[(size_t)MROWS * DDIM];
__device__ __align__(256) __half g_gh [(size_t)MROWS * DH];
// fp16 transposed weights W^T [N, K] (K contiguous)
__device__ __align__(256) __half g_wqk[(size_t)256 * DDIM];
__device__ __align__(256) __half g_wlo[(size_t)DDIM * DDIM];
__device__ __align__(256) __half g_wlp[(size_t)FDIM * DDIM];
__device__ __align__(256) __half g_wpj[(size_t)DDIM * FDIM];
__device__ __align__(256) __half g_wo [(size_t)DDIM * DH];

// ======================= helpers =======================
__device__ __forceinline__ uint32_t smem_u32(const void* p) {
    uint32_t a;
    asm("{ .reg .u64 t; cvta.to.shared.u64 t, %1; cvt.u32.u64 %0, t; }" : "=r"(a) : "l"(p));
    return a;
}
__device__ __forceinline__ void ldx4(uint32_t* r, uint32_t addr) {
    asm volatile("ldmatrix.sync.aligned.m8n8.x4.shared.b16 {%0,%1,%2,%3}, [%4];"
        : "=r"(r[0]), "=r"(r[1]), "=r"(r[2]), "=r"(r[3]) : "r"(addr));
}
__device__ __forceinline__ void mma_fp16(float* c, const uint32_t* a, const uint32_t* b) {
    asm volatile("mma.sync.aligned.m16n8k16.row.col.f32.f16.f16.f32 "
        "{%0,%1,%2,%3}, {%4,%5,%6,%7}, {%8,%9}, {%0,%1,%2,%3};"
        : "+f"(c[0]), "+f"(c[1]), "+f"(c[2]), "+f"(c[3])
        : "r"(a[0]), "r"(a[1]), "r"(a[2]), "r"(a[3]), "r"(b[0]), "r"(b[1]));
}
__device__ __forceinline__ float sigm(float x) { return 1.0f / (1.0f + __expf(-x)); }
__device__ __forceinline__ float gelu_f(float x) {
    float z  = 0.7978845608028654f * (x + 0.044715f * x * x * x);
    float az = fabsf(z);
    float e  = __expf(-2.0f * az);
    float t  = (1.0f - e) / (1.0f + e);
    t = copysignf(t, z);
    return 0.5f * x * (1.0f + t);
}
__device__ __forceinline__ uint32_t pack2(__half a, __half b) {
    return (uint32_t)__half_as_ushort(a) | ((uint32_t)__half_as_ushort(b) << 16);
}

// BK=64: 128B data per row + 16B pad = 144B row stride (conflict-free ldmatrix).
#define RSTR2 144

// ======================= fp16 HMMA GEMM (wide: 128x256, 512 thr) =============
// C[M,N] = A[M,K](fp16) @ B^T[N,K](fp16). BK=64, 4-stage cp.async pipeline.
// 16 warps (2x8), warp tile 64x32.
// EPI 0: Cf = acc + bias (f32). EPI 1: gelu(acc+bias) -> Ch (fp16).
// EPI 2: acc + bias -> Ch (fp16).
#define AT512  18432          // 128*RSTR2
#define STG512 55296          // (128+256)*RSTR2
#define SM512  221184         // 4 stages

template <int EPI>
__global__ void __launch_bounds__(512, 1) hgemm512(
    const __half* __restrict__ Ap, const __half* __restrict__ Bp,
    const float* __restrict__ bias,
    float* __restrict__ Cf, __half* __restrict__ Ch,
    int N, int K)
{
    extern __shared__ char smem[];
    const uint32_t sbase = smem_u32(smem);
    const int tid  = threadIdx.x;
    const int wid  = tid >> 5, lane = tid & 31;
    const long bm  = (long)blockIdx.y * 128;
    const long bn  = (long)blockIdx.x * 256;
    const int  wm  = wid >> 3, wn = wid & 7;
    const long kb  = (long)K * 2;

    const char* baseA = (const char*)Ap + bm * kb;
    const char* baseB = (const char*)Bp + bn * kb;
    const int crow = tid >> 3, ccol = tid & 7;   // 8x16B chunks = 128B row

    auto load_stage = [&](int kt, int slot) {
        const uint32_t so = sbase + slot * STG512;
        const long gk = (long)kt * 128 + ccol * 16;
#pragma unroll
        for (int c = 0; c < 2; ++c) {
            const int row = crow + c * 64;
            asm volatile("cp.async.cg.shared.global [%0], [%1], 16;"
                :: "r"(so + row * RSTR2 + ccol * 16), "l"(baseA + (long)row * kb + gk));
        }
#pragma unroll
        for (int c = 0; c < 4; ++c) {
            const int row = crow + c * 64;
            asm volatile("cp.async.cg.shared.global [%0], [%1], 16;"
                :: "r"(so + AT512 + row * RSTR2 + ccol * 16), "l"(baseB + (long)row * kb + gk));
        }
        asm volatile("cp.async.commit_group;" ::: "memory");
    };

    const uint32_t g  = lane >> 3, li = lane & 7;
    const uint32_t aRow = wm * 64 + ((g & 1) << 3) + li;
    const uint32_t aCol = (g >> 1) << 4;
    const uint32_t bRow = wn * 32 + ((g >> 1) << 3) + li;
    const uint32_t bCol = (g & 1) << 4;

    float acc[4][4][4];
#pragma unroll
    for (int i = 0; i < 4; ++i)
#pragma unroll
        for (int j = 0; j < 4; ++j)
#pragma unroll
            for (int q = 0; q < 4; ++q) acc[i][j][q] = 0.f;

    const int nk = K >> 6;
    load_stage(0, 0);
    if (nk > 1) load_stage(1, 1);
    if (nk > 2) load_stage(2, 2);

    for (int kt = 0; kt < nk; ++kt) {
        if (kt <= nk - 3)      asm volatile("cp.async.wait_group 2;" ::: "memory");
        else if (kt == nk - 2) asm volatile("cp.async.wait_group 1;" ::: "memory");
        else                   asm volatile("cp.async.wait_group 0;" ::: "memory");
        __syncthreads();
        if (kt + 3 < nk) load_stage(kt + 3, (kt + 3) & 3);

        const uint32_t so = sbase + (kt & 3) * STG512;
#pragma unroll
        for (int kk = 0; kk < 4; ++kk) {
            uint32_t ah[4][4], bh[4][2];
#pragma unroll
            for (int mt = 0; mt < 4; ++mt)
                ldx4(ah[mt], so + (aRow + mt * 16) * RSTR2 + kk * 32 + aCol);
#pragma unroll
            for (int p = 0; p < 2; ++p) {
                uint32_t r[4];
                ldx4(r, so + AT512 + (bRow + p * 16) * RSTR2 + kk * 32 + bCol);
                bh[2*p][0] = r[0]; bh[2*p][1] = r[1];
                bh[2*p+1][0] = r[2]; bh[2*p+1][1] = r[3];
            }
#pragma unroll
            for (int mt = 0; mt < 4; ++mt)
#pragma unroll
                for (int nt = 0; nt < 4; ++nt)
                    mma_fp16(acc[mt][nt], ah[mt], bh[nt]);
        }
    }

#pragma unroll
    for (int mt = 0; mt < 4; ++mt) {
        const long r0 = bm + wm * 64 + mt * 16 + (lane >> 2);
#pragma unroll
        for (int nt = 0; nt < 4; ++nt) {
            const long cc = bn + wn * 32 + nt * 8 + (lane & 3) * 2;
            const float2 bv = *(const float2*)(bias + cc);
            float v0 = acc[mt][nt][0] + bv.x, v1 = acc[mt][nt][1] + bv.y;
            float v2 = acc[mt][nt][2] + bv.x, v3 = acc[mt][nt][3] + bv.y;
            if (EPI == 0) {
                *(float2*)(Cf + r0 * N + cc)       = make_float2(v0, v1);
                *(float2*)(Cf + (r0 + 8) * N + cc) = make_float2(v2, v3);
            } else if (EPI == 1) {
                *(uint32_t*)(Ch + r0 * N + cc) =
                    pack2(__float2half_rn(gelu_f(v0)), __float2half_rn(gelu_f(v1)));
                *(uint32_t*)(Ch + (r0 + 8) * N + cc) =
                    pack2(__float2half_rn(gelu_f(v2)), __float2half_rn(gelu_f(v3)));
            } else {  // EPI 2: plain fp16 out
                *(uint32_t*)(Ch + r0 * N + cc) =
                    pack2(__float2half_rn(v0), __float2half_rn(v1));
                *(uint32_t*)(Ch + (r0 + 8) * N + cc) =
                    pack2(__float2half_rn(v2), __float2half_rn(v3));
            }
        }
    }
}

// ======================= fp16 GEMM (narrow: 128x128, 256 thr, occ 2) =========
// BK=64, 3-stage. Cf = acc + bias.
#define STG256 36864          // 2*128*RSTR2
#define SM256  110592         // 3 stages

__global__ void __launch_bounds__(256, 2) hgemm256(
    const __half* __restrict__ Ap, const __half* __restrict__ Bp,
    const float* __restrict__ bias, float* __restrict__ Cf,
    int N, int K)
{
    extern __shared__ char smem[];
    const uint32_t sbase = smem_u32(smem);
    const int tid  = threadIdx.x;
    const int wid  = tid >> 5, lane = tid & 31;
    const long bm  = (long)blockIdx.y * 128;
    const long bn  = (long)blockIdx.x * 128;
    const int  wm  = wid >> 2, wn = wid & 3;
    const long kb  = (long)K * 2;

    const char* baseA = (const char*)Ap + bm * kb;
    const char* baseB = (const char*)Bp + bn * kb;
    const int crow = tid >> 3, ccol = tid & 7;

    auto load_stage = [&](int kt, int slot) {
        const uint32_t so = sbase + slot * STG256;
        const long gk = (long)kt * 128 + ccol * 16;
#pragma unroll
        for (int c = 0; c < 4; ++c) {
            const int row = crow + c * 32;
            asm volatile("cp.async.cg.shared.global [%0], [%1], 16;"
                :: "r"(so + row * RSTR2 + ccol * 16), "l"(baseA + (long)row * kb + gk));
            asm volatile("cp.async.cg.shared.global [%0], [%1], 16;"
                :: "r"(so + AT512 + row * RSTR2 + ccol * 16), "l"(baseB + (long)row * kb + gk));
        }
        asm volatile("cp.async.commit_group;" ::: "memory");
    };

    const uint32_t g  = lane >> 3, li = lane & 7;
    const uint32_t aRow = wm * 64 + ((g & 1) << 3) + li;
    const uint32_t aCol = (g >> 1) << 4;
    const uint32_t bRow = wn * 32 + ((g >> 1) << 3) + li;
    const uint32_t bCol = (g & 1) << 4;

    float acc[4][4][4];
#pragma unroll
    for (int i = 0; i < 4; ++i)
#pragma unroll
        for (int j = 0; j < 4; ++j)
#pragma unroll
            for (int q = 0; q < 4; ++q) acc[i][j][q] = 0.f;

    const int nk = K >> 6;
    load_stage(0, 0);
    if (nk > 1) load_stage(1, 1);

    for (int kt = 0; kt < nk; ++kt) {
        if (kt + 1 < nk) asm volatile("cp.async.wait_group 1;" ::: "memory");
        else             asm volatile("cp.async.wait_group 0;" ::: "memory");
        __syncthreads();
        if (kt + 2 < nk) load_stage(kt + 2, (kt + 2) % 3);

        const uint32_t so = sbase + (kt % 3) * STG256;
#pragma unroll
        for (int kk = 0; kk < 4; ++kk) {
            uint32_t ah[4][4], bh[4][2];
#pragma unroll
            for (int mt = 0; mt < 4; ++mt)
                ldx4(ah[mt], so + (aRow + mt * 16) * RSTR2 + kk * 32 + aCol);
#pragma unroll
            for (int p = 0; p < 2; ++p) {
                uint32_t r[4];
                ldx4(r, so + AT512 + (bRow + p * 16) * RSTR2 + kk * 32 + bCol);
                bh[2*p][0] = r[0]; bh[2*p][1] = r[1];
                bh[2*p+1][0] = r[2]; bh[2*p+1][1] = r[3];
            }
#pragma unroll
            for (int mt = 0; mt < 4; ++mt)
#pragma unroll
                for (int nt = 0; nt < 4; ++nt)
                    mma_fp16(acc[mt][nt], ah[mt], bh[nt]);
        }
    }

#pragma unroll
    for (int mt = 0; mt < 4; ++mt) {
        const long r0 = bm + wm * 64 + mt * 16 + (lane >> 2);
#pragma unroll
        for (int nt = 0; nt < 4; ++nt) {
            const long cc = bn + wn * 32 + nt * 8 + (lane & 3) * 2;
            const float2 bv = *(const float2*)(bias + cc);
            *(float2*)(Cf + r0 * N + cc) =
                make_float2(acc[mt][nt][0] + bv.x, acc[mt][nt][1] + bv.y);
            *(float2*)(Cf + (r0 + 8) * N + cc) =
                make_float2(acc[mt][nt][2] + bv.x, acc[mt][nt][3] + bv.y);
        }
    }
}

// ======================= weight transpose -> fp16 =======================
__global__ void tsplit_kernel(const float* __restrict__ W,
                              __half* __restrict__ th, int K, int N, int rowoff)
{
    __shared__ float t[32][33];
    const int k0 = blockIdx.y * 32, n0 = blockIdx.x * 32;
    const int tx = threadIdx.x, ty = threadIdx.y;
#pragma unroll
    for (int i = ty; i < 32; i += 8)
        t[i][tx] = W[(long)(k0 + i) * N + n0 + tx];
    __syncthreads();
#pragma unroll
    for (int i = ty; i < 32; i += 8) {
        const long n = n0 + i, k = k0 + tx;
        th[(rowoff + n) * (long)K + k] = __float2half_rn(t[tx][i]);
    }
}

// ======================= x -> fp16 =======================
__global__ void cvt_kernel(const float* __restrict__ x, __half* __restrict__ h, long n4)
{
    long i = (long)blockIdx.x * blockDim.x + threadIdx.x;
    if (i >= n4) return;
    float4 v = ((const float4*)x)[i];
    ((uint2*)h)[i] = make_uint2(
        pack2(__float2half_rn(v.x), __float2half_rn(v.y)),
        pack2(__float2half_rn(v.z), __float2half_rn(v.w)));
}

__global__ void bqk_kernel(const float* __restrict__ Qb, const float* __restrict__ Kb,
                           float* __restrict__ b)
{
    int i = threadIdx.x;
    b[i] = (i < 128) ? Qb[i] : Kb[i - 128];
}

// ======================= score = sigmoid(q)*sigmoid(k) =======================
__global__ void score_kernel(const float* __restrict__ qk, float* __restrict__ s)
{
    long i = (long)blockIdx.x * blockDim.x + threadIdx.x;
    long m = i >> 7;
    int  f = (int)(i & 127);
    s[i] = sigm(qk[m * 256 + f]) * sigm(qk[m * 256 + 128 + f]);
}

// ======================= chunked EMA scan over time =======================
#define EMA_CHUNK 128
#define EMA_WARM  256
__global__ void ema_kernel(const float* __restrict__ sc, float* __restrict__ ema)
{
    const int b  = blockIdx.y;
    const int t0 = blockIdx.x * EMA_CHUNK;
    const int f  = threadIdx.x;
    const float* sb = sc  + ((long)b * SEQ) * FDIM + f;
    float*       eb = ema + ((long)b * SEQ) * FDIM + f;

    int   t = t0 - EMA_WARM;
    float prev;
    if (t <= 0) {
        prev = sb[0];
        if (t0 == 0) eb[0] = prev;
        t = 1;
    } else {
        prev = 0.0f;
    }
    const int tend = t0 + EMA_CHUNK;
    for (; t < tend; ++t) {
        float s = sb[(long)t * FDIM];
        prev = 0.15f * s + 0.85f * prev;
        if (t >= t0) eb[(long)t * FDIM] = prev;
    }
}

// ======================= mean/clip * V -> fp16 =======================
__global__ void normclip_kernel(const float* __restrict__ ema, const float* __restrict__ V,
                                __half* __restrict__ xh)
{
    const long row = blockIdx.x;
    const int  f   = threadIdx.x;  // 128
    float e = ema[row * FDIM + f];
    float s = e;
#pragma unroll
    for (int o = 16; o; o >>= 1) s += __shfl_xor_sync(0xffffffffu, s, o);
    __shared__ float ws[4];
    if ((f & 31) == 0) ws[f >> 5] = s;
    __syncthreads();
    float tot = ws[0] + ws[1] + ws[2] + ws[3];
    float denom = fmaxf(tot * (1.0f / 128.0f), 1e-6f);
    float c = e / denom;
    c = fminf(fmaxf(c, -5.0f), 5.0f);
    xh[row * FDIM + f] = __float2half_rn(c * V[row * FDIM + f]);
}

// ======================= SwiGLU gate (fp16 in) -> fp16 =======================
__global__ void gate_kernel(const __half* __restrict__ o1, __half* __restrict__ gh)
{
    long i = (long)blockIdx.x * blockDim.x + threadIdx.x;  // over half2 units
    long m = i >> 9;           // 512 half2 per row half (1024 elems)
    int  j = (int)(i & 511);
    const __half2* a2 = (const __half2*)(o1 + m * DDIM) + j;
    const __half2* b2 = (const __half2*)(o1 + m * DDIM + DH) + j;
    float2 a = __half22float2(*a2);
    float2 b = __half22float2(*b2);
    float g0 = (a.x * sigm(a.x)) * b.x;
    float g1 = (a.y * sigm(a.y)) * b.y;
    ((uint32_t*)gh)[i] = pack2(__float2half_rn(g0), __float2half_rn(g1));
}

// ======================= residual + LayerNorm =======================
__global__ void __launch_bounds__(256) ln_kernel(
    const float* __restrict__ o2, const float* __restrict__ x,
    const float* __restrict__ gamma, const float* __restrict__ beta,
    float* __restrict__ y)
{
    __shared__ float ws[8];
    const long row = blockIdx.x;
    const int  tid = threadIdx.x;
    const float* pr = o2 + row * DDIM;
    const float* px = x  + row * DDIM;
    const int c0 = tid * 4;
    const int c1 = 1024 + tid * 4;

    float4 a0 = *(const float4*)(pr + c0), r0 = *(const float4*)(px + c0);
    float4 a1 = *(const float4*)(pr + c1), r1 = *(const float4*)(px + c1);
    float h[8] = { a0.x + r0.x, a0.y + r0.y, a0.z + r0.z, a0.w + r0.w,
                   a1.x + r1.x, a1.y + r1.y, a1.z + r1.z, a1.w + r1.w };

    float s = 0.f;
#pragma unroll
    for (int i = 0; i < 8; ++i) s += h[i];
#pragma unroll
    for (int o = 16; o; o >>= 1) s += __shfl_xor_sync(0xffffffffu, s, o);
    if ((tid & 31) == 0) ws[tid >> 5] = s;
    __syncthreads();
    float tot = 0.f;
#pragma unroll
    for (int i = 0; i < 8; ++i) tot += ws[i];
    const float mu = tot * (1.0f / 2048.0f);
    __syncthreads();

    float sq = 0.f;
#pragma unroll
    for (int i = 0; i < 8; ++i) { float d = h[i] - mu; sq += d * d; }
#pragma unroll
    for (int o = 16; o; o >>= 1) sq += __shfl_xor_sync(0xffffffffu, sq, o);
    if ((tid & 31) == 0) ws[tid >> 5] = sq;
    __syncthreads();
    float tot2 = 0.f;
#pragma unroll
    for (int i = 0; i < 8; ++i) tot2 += ws[i];
    const float inv = rsqrtf(tot2 * (1.0f / 2048.0f) + 1e-5f);

    float4 g0 = *(const float4*)(gamma + c0), g1 = *(const float4*)(gamma + c1);
    float4 b0 = *(const float4*)(beta  + c0), b1 = *(const float4*)(beta  + c1);
    float4 y0, y1;
    y0.x = (h[0] - mu) * inv * g0.x + b0.x;
    y0.y = (h[1] - mu) * inv * g0.y + b0.y;
    y0.z = (h[2] - mu) * inv * g0.z + b0.z;
    y0.w = (h[3] - mu) * inv * g0.w + b0.w;
    y1.x = (h[4] - mu) * inv * g1.x + b1.x;
    y1.y = (h[5] - mu) * inv * g1.y + b1.y;
    y1.z = (h[6] - mu) * inv * g1.z + b1.z;
    y1.w = (h[7] - mu) * inv * g1.w + b1.w;
    *(float4*)(y + row * DDIM + c0) = y0;
    *(float4*)(y + row * DDIM + c1) = y1;
}

// ======================= launch =======================
extern "C" void kernel_launch(void* const* d_in, const int* in_sizes, int n_in,
                              void* d_out, int out_size)
{
    const float* x      = (const float*)d_in[0];
    const float* Qw     = (const float*)d_in[1];
    const float* Qb     = (const float*)d_in[2];
    const float* Kw     = (const float*)d_in[3];
    const float* Kb     = (const float*)d_in[4];
    const float* low    = (const float*)d_in[5];
    const float* lob    = (const float*)d_in[6];
    const float* lopw   = (const float*)d_in[7];
    const float* lopb   = (const float*)d_in[8];
    const float* projw  = (const float*)d_in[9];
    const float* projb  = (const float*)d_in[10];
    const float* Ow     = (const float*)d_in[11];
    const float* Ob     = (const float*)d_in[12];
    const float* gamma  = (const float*)d_in[13];
    const float* beta   = (const float*)d_in[14];
    float* out = (float*)d_out;

    float *qk, *sc, *em, *V, *o2, *bqk;
    __half *xh, *Hh, *xch, *o1h, *gh;
    __half *wqk, *wlo, *wlp, *wpj, *wo;
    cudaGetSymbolAddress((void**)&qk,  g_qk);
    cudaGetSymbolAddress((void**)&sc,  g_sc);
    cudaGetSymbolAddress((void**)&em,  g_em);
    cudaGetSymbolAddress((void**)&V,   g_V);
    cudaGetSymbolAddress((void**)&o2,  g_o2);
    cudaGetSymbolAddress((void**)&bqk, g_bqk);
    cudaGetSymbolAddress((void**)&xh,  g_xh);
    cudaGetSymbolAddress((void**)&Hh,  g_Hh);
    cudaGetSymbolAddress((void**)&xch, g_xch);
    cudaGetSymbolAddress((void**)&o1h, g_o1h);
    cudaGetSymbolAddress((void**)&gh,  g_gh);
    cudaGetSymbolAddress((void**)&wqk, g_wqk);
    cudaGetSymbolAddress((void**)&wlo, g_wlo);
    cudaGetSymbolAddress((void**)&wlp, g_wlp);
    cudaGetSymbolAddress((void**)&wpj, g_wpj);
    cudaGetSymbolAddress((void**)&wo,  g_wo);

    cudaFuncSetAttribute(hgemm512<0>, cudaFuncAttributeMaxDynamicSharedMemorySize, SM512);
    cudaFuncSetAttribute(hgemm512<1>, cudaFuncAttributeMaxDynamicSharedMemorySize, SM512);
    cudaFuncSetAttribute(hgemm512<2>, cudaFuncAttributeMaxDynamicSharedMemorySize, SM512);
    cudaFuncSetAttribute(hgemm256,    cudaFuncAttributeMaxDynamicSharedMemorySize, SM256);

    const dim3 tb32(32, 8);
    // weight prep + x convert
    tsplit_kernel<<<dim3(DDIM/32, DDIM/32), tb32>>>(low,  wlo, DDIM, DDIM, 0);
    {
        long n4 = (long)MROWS * DDIM / 4;
        cvt_kernel<<<(unsigned)((n4 + 255) / 256), 256>>>(x, xh, n4);
    }
    bqk_kernel<<<1, 256>>>(Qb, Kb, bqk);
    tsplit_kernel<<<dim3(FDIM/32, DDIM/32), tb32>>>(Qw, wqk, DDIM, FDIM, 0);
    tsplit_kernel<<<dim3(FDIM/32, DDIM/32), tb32>>>(Kw, wqk, DDIM, FDIM, 128);
    // H = gelu(x @ lo_proj_w + b) -> fp16
    hgemm512<1><<<dim3(DDIM/256, MROWS/128), 512, SM512>>>(xh, wlo, lob, nullptr, Hh, DDIM, DDIM);
    // remaining weight prep
    tsplit_kernel<<<dim3(FDIM/32, DDIM/32), tb32>>>(lopw, wlp, DDIM, FDIM, 0);
    tsplit_kernel<<<dim3(DDIM/32, FDIM/32), tb32>>>(projw,wpj, FDIM, DDIM, 0);
    tsplit_kernel<<<dim3(DDIM/32, DH/32),   tb32>>>(Ow, wo, DH, DDIM, 0);
    // qk = x @ [Qw|Kw] + [Qb|Kb]
    hgemm256<<<dim3(2, MROWS/128), 256, SM256>>>(xh, wqk, bqk, qk, 256, DDIM);
    score_kernel<<<(MROWS * FDIM) / 256, 256>>>(qk, sc);
    // V = H @ lo_p_w + b
    hgemm256<<<dim3(1, MROWS/128), 256, SM256>>>(Hh, wlp, lopb, V, FDIM, DDIM);
    // EMA, norm/clip
    ema_kernel<<<dim3(SEQ / EMA_CHUNK, NBATCH), 128>>>(sc, em);
    normclip_kernel<<<MROWS, 128>>>(em, V, xch);
    // o1 = xc @ proj_w + b  (fp16 out)
    hgemm512<2><<<dim3(DDIM/256, MROWS/128), 512, SM512>>>(xch, wpj, projb, nullptr, o1h, DDIM, FDIM);
    // gate
    gate_kernel<<<(MROWS * DH / 2) / 256, 256>>>(o1h, gh);
    // o2 = g @ O_w + b
    hgemm512<0><<<dim3(DDIM/256, MROWS/128), 512, SM512>>>(gh, wo, Ob, o2, nullptr, DDIM, DH);
    // residual + LN
    ln_kernel<<<MROWS, 256>>>(o2, x, gamma, beta, out);
}